// round 12
// baseline (speedup 1.0000x reference)
#include <cuda_runtime.h>
#include <cuda_bf16.h>

#define S_LEN 512
#define HID   500
#define G3    1500
#define VOC   50000
#define NVT   391          // ceil(50000/128)
#define RBLK  25           // recurrence blocks
#define RWPB  20           // compute warps per recurrence block (25*20 = 500)

// ---------------- static device scratch ----------------
__device__ float gGiEnc[S_LEN * G3];
__device__ float gGiDec[S_LEN * G3];
// mailbox lines: [parity][block] = 128B line: 20 h floats + flag word at [31]
__device__ __align__(128) float gHx[2][RBLK][32];
__device__ __align__(16) float gHfinal[512];
__device__ float gDecHs[S_LEN * HID];
__device__ float gPmax[S_LEN * NVT];
__device__ float gPsum[S_LEN * NVT];
__device__ int   gPidx[S_LEN * NVT];
__device__ float gTlogit[S_LEN];
__device__ float gNll[S_LEN];

// ---------------- helpers ----------------
__device__ __forceinline__ unsigned long long f22ull(float x, float y) {
    unsigned long long u;
    asm("mov.b64 %0, {%1, %2};" : "=l"(u) : "f"(x), "f"(y));
    return u;
}
__device__ __forceinline__ void ull2f2(unsigned long long u, float& x, float& y) {
    asm("mov.b64 {%0, %1}, %2;" : "=f"(x), "=f"(y) : "l"(u));
}
__device__ __forceinline__ void ffma2(unsigned long long& d, unsigned long long a, unsigned long long b) {
    asm("fma.rn.f32x2 %0, %1, %2, %0;" : "+l"(d) : "l"(a), "l"(b));
}
__device__ __forceinline__ unsigned ld_acq(const unsigned* p) {
    unsigned v;
    asm volatile("ld.acquire.gpu.global.u32 %0, [%1];" : "=r"(v) : "l"(p) : "memory");
    return v;
}
__device__ __forceinline__ void st_rel(unsigned* p, unsigned v) {
    asm volatile("st.release.gpu.global.u32 [%0], %1;" :: "l"(p), "r"(v) : "memory");
}
__device__ __forceinline__ unsigned smem_u32(const void* p) {
    return (unsigned)__cvta_generic_to_shared(p);
}
#define CP_ASYNC8(dst, src, sz) \
    asm volatile("cp.async.ca.shared.global [%0], [%1], 8, %2;" \
                 :: "r"(dst), "l"(src), "r"(sz) : "memory")
#define CP_COMMIT() asm volatile("cp.async.commit_group;" ::: "memory")

__device__ __forceinline__ float sigmoid_fast(float x) {
    return __fdividef(1.f, 1.f + __expf(-x));
}
__device__ __forceinline__ float tanh_fast(float x) {
    return __fdividef(2.f, 1.f + __expf(-2.f * x)) - 1.f;
}

// =====================================================================
// K0: reset mailbox flags/data (replay safety).
// =====================================================================
__global__ void reset_kernel() {
    int i = blockIdx.x * blockDim.x + threadIdx.x;
    if (i < 2 * RBLK * 32) ((float*)gHx)[i] = 0.f;
}

// =====================================================================
// K1: gi = gather(emb, tok)[relu if dec] @ Wih^T + bih   for enc & dec
// grid (12, 4, 2). Conflict-free B fragments.
// =====================================================================
__global__ __launch_bounds__(256, 1) void gi_gemm_kernel(
    const int* __restrict__ encTok, const int* __restrict__ tgtTok,
    const float* __restrict__ encEmb, const float* __restrict__ decEmb,
    const float* __restrict__ encWih, const float* __restrict__ decWih,
    const float* __restrict__ encBih, const float* __restrict__ decBih)
{
    const int mode = blockIdx.z;
    const float* emb  = mode ? decEmb : encEmb;
    const float* W    = mode ? decWih : encWih;
    const float* bias = mode ? decBih : encBih;
    float* out = mode ? gGiDec : gGiEnc;

    const int t0 = blockIdx.y * 128;
    const int g0 = blockIdx.x * 128;

    __shared__ __align__(16) unsigned long long As[10][128];
    __shared__ __align__(16) unsigned long long Bs[10][128];
    __shared__ int   sTok[128];
    __shared__ float sBias[128];

    const int tid = threadIdx.x;
    if (tid < 128) {
        int t = t0 + tid;
        int tok;
        if (mode) tok = (t == 0) ? 0 : tgtTok[t - 1];   // teacher forcing, PAD first
        else      tok = encTok[t];
        sTok[tid] = tok;
        int g = g0 + tid;
        sBias[tid] = (g < G3) ? bias[g] : 0.f;
    }
    __syncthreads();

    unsigned long long acc[8][8];
#pragma unroll
    for (int i = 0; i < 8; i++)
#pragma unroll
        for (int j = 0; j < 8; j++) acc[i][j] = 0ull;

    const int ty = tid >> 4, tx = tid & 15;

    for (int kc = 0; kc < 25; kc++) {
        const int kb = kc * 20;
#pragma unroll
        for (int r = 0; r < 5; r++) {
            int id  = tid + r * 256;
            int k2  = id >> 7;
            int col = id & 127;
            const float* ap = emb + (size_t)sTok[col] * HID + kb + k2 * 2;
            float2 av = *(const float2*)ap;
            if (mode) { av.x = fmaxf(av.x, 0.f); av.y = fmaxf(av.y, 0.f); }
            As[k2][col] = f22ull(av.x, av.y);
            int g = g0 + col;
            float2 bv = make_float2(0.f, 0.f);
            if (g < G3) bv = *(const float2*)(W + (size_t)g * HID + kb + k2 * 2);
            Bs[k2][col] = f22ull(bv.x, bv.y);
        }
        __syncthreads();
#pragma unroll
        for (int k2 = 0; k2 < 10; k2++) {
            unsigned long long a[8], b[8];
            const ulonglong2* ap = (const ulonglong2*)&As[k2][ty << 3];
            ulonglong2 q;
            q = ap[0]; a[0] = q.x; a[1] = q.y;
            q = ap[1]; a[2] = q.x; a[3] = q.y;
            q = ap[2]; a[4] = q.x; a[5] = q.y;
            q = ap[3]; a[6] = q.x; a[7] = q.y;
#pragma unroll
            for (int m = 0; m < 8; m++) b[m] = Bs[k2][tx + (m << 4)];
#pragma unroll
            for (int i = 0; i < 8; i++)
#pragma unroll
                for (int j = 0; j < 8; j++) ffma2(acc[i][j], a[i], b[j]);
        }
        __syncthreads();
    }

#pragma unroll
    for (int i = 0; i < 8; i++) {
        int t = t0 + (ty << 3) + i;
#pragma unroll
        for (int m = 0; m < 8; m++) {
            int g = g0 + tx + (m << 4);
            if (g < G3) {
                float x, y; ull2f2(acc[i][m], x, y);
                out[(size_t)t * G3 + g] = x + y + sBias[tx + (m << 4)];
            }
        }
    }
}

// =====================================================================
// K2: GRU recurrence. 25 blocks x 672 threads.
// Warps 0-19 compute (one hidden unit each, f32x2 packed weights in regs).
// Warp 20 = dedicated producer (mailbox line + release flag).
// Warp 0 lanes 0-24 = consumers (poll 25 lines, pull into smem).
// =====================================================================
__global__ __launch_bounds__(672, 1) void gru_rec_kernel(
    const float* __restrict__ Whh, const float* __restrict__ bhh,
    const float* __restrict__ h0_in, float* __restrict__ dOut,
    int mode, unsigned flagBase)
{
    const float* gi = mode ? gGiDec : gGiEnc;
    const int tid  = threadIdx.x;
    const int warp = tid >> 5;
    const int lane = tid & 31;
    const int j = blockIdx.x * RWPB + warp;   // valid for warp<20

    __shared__ __align__(16) float sH[512];
    __shared__ __align__(16) float sStage[24];

    // packed weights: ull i holds weights for k = pairbase(i)
    unsigned long long wr2[8], wz2[8], wn2[8];
    float br = 0.f, bz = 0.f, bn = 0.f;
    if (warp < RWPB) {
#pragma unroll
        for (int i = 0; i < 4; i++) {
            int kb = (i << 7) + (lane << 2);
            float4 a = make_float4(0.f,0.f,0.f,0.f), b = a, c = a;
            if (kb + 3 < HID) {
                a = *(const float4*)(Whh + (size_t)j * HID + kb);
                b = *(const float4*)(Whh + (size_t)(j + HID) * HID + kb);
                c = *(const float4*)(Whh + (size_t)(j + 2 * HID) * HID + kb);
            }
            wr2[i*2+0] = f22ull(a.x, a.y); wr2[i*2+1] = f22ull(a.z, a.w);
            wz2[i*2+0] = f22ull(b.x, b.y); wz2[i*2+1] = f22ull(b.z, b.w);
            wn2[i*2+0] = f22ull(c.x, c.y); wn2[i*2+1] = f22ull(c.z, c.w);
        }
        br = bhh[j]; bz = bhh[j + HID]; bn = bhh[j + 2 * HID];
    }

    // init sH (pad 500..511 = 0; never written afterwards)
    if (tid < 128) {
        float4 v = make_float4(0.f, 0.f, 0.f, 0.f);
        if (tid < 125) {
            if (mode) v = *(const float4*)(gHfinal + tid * 4);
            else      v = *(const float4*)(h0_in + tid * 4);
        }
        *(float4*)(sH + tid * 4) = v;
    }

    float gir = 0.f, giz = 0.f, gin = 0.f;
    if (warp < RWPB && lane == 0) {
        const float* g0 = gi + j;
        gir = g0[0]; giz = g0[HID]; gin = g0[2 * HID];
    }
    __syncthreads();

    for (int s = 0; s < S_LEN; s++) {
        if (warp < RWPB) {
            // packed h from shared: 4 x ulonglong2
            unsigned long long h2[8];
#pragma unroll
            for (int i = 0; i < 4; i++) {
                ulonglong2 q = *(const ulonglong2*)(sH + (i << 7) + (lane << 2));
                h2[i*2] = q.x; h2[i*2+1] = q.y;
            }
            float hold = 0.f;
            if (lane == 0) hold = sH[j];

            unsigned long long aR = 0ull, aZ = 0ull, aN = 0ull;
#pragma unroll
            for (int i = 0; i < 8; i++) {
                ffma2(aR, wr2[i], h2[i]);
                ffma2(aZ, wz2[i], h2[i]);
                ffma2(aN, wn2[i], h2[i]);
            }
            float x, y;
            ull2f2(aR, x, y); float ar = x + y;
            ull2f2(aZ, x, y); float az = x + y;
            ull2f2(aN, x, y); float an = x + y;
#pragma unroll
            for (int off = 16; off; off >>= 1) {
                ar += __shfl_xor_sync(0xffffffffu, ar, off);
                az += __shfl_xor_sync(0xffffffffu, az, off);
                an += __shfl_xor_sync(0xffffffffu, an, off);
            }
            if (lane == 0) {
                float r = sigmoid_fast(gir + ar + br);
                float z = sigmoid_fast(giz + az + bz);
                float n = tanh_fast(gin + r * (an + bn));
                sStage[warp] = (1.f - z) * n + z * hold;
                if (s + 1 < S_LEN) {           // prefetch next gi (hidden under exchange)
                    const float* gs = gi + (size_t)(s + 1) * G3 + j;
                    gir = gs[0]; giz = gs[HID]; gin = gs[2 * HID];
                }
            }
        }
        __syncthreads();                        // A: sStage complete, sH reads done

        const unsigned want = flagBase + 1u + (unsigned)s;
        if (warp == RWPB) {
            // dedicated producer: post the block's line + release flag
            if (lane == 0) {
                float* line = gHx[s & 1][blockIdx.x];
                float4 d0 = *(const float4*)(sStage + 0);
                float4 d1 = *(const float4*)(sStage + 4);
                float4 d2 = *(const float4*)(sStage + 8);
                float4 d3 = *(const float4*)(sStage + 12);
                float4 d4 = *(const float4*)(sStage + 16);
                __stcg((float4*)line + 0, d0);
                __stcg((float4*)line + 1, d1);
                __stcg((float4*)line + 2, d2);
                __stcg((float4*)line + 3, d3);
                __stcg((float4*)line + 4, d4);
                st_rel((unsigned*)(line + 31), want);
            }
            // decoder hs: consumed after kernel end; no ordering needed
            if (mode && lane < RWPB) {
                __stcg(gDecHs + (size_t)s * HID + blockIdx.x * RWPB + lane, sStage[lane]);
            }
        } else if (warp == 0 && lane < RBLK) {
            // consumers: one line per lane; flag+data share the line
            const float* line = gHx[s & 1][lane];
            const unsigned* fp = (const unsigned*)(line + 31);
            while (ld_acq(fp) < want) { }
            float4 v0 = __ldcg((const float4*)line + 0);
            float4 v1 = __ldcg((const float4*)line + 1);
            float4 v2 = __ldcg((const float4*)line + 2);
            float4 v3 = __ldcg((const float4*)line + 3);
            float4 v4 = __ldcg((const float4*)line + 4);
            float* dst = sH + lane * RWPB;
            *(float4*)(dst + 0)  = v0;
            *(float4*)(dst + 4)  = v1;
            *(float4*)(dst + 8)  = v2;
            *(float4*)(dst + 12) = v3;
            *(float4*)(dst + 16) = v4;
        }
        __syncthreads();                        // B: sH holds step-s result
    }

    if (!mode && blockIdx.x == 0) {
        for (int i = tid; i < 512; i += 672) gHfinal[i] = sH[i];
        for (int i = tid; i < HID; i += 672) dOut[1 + i] = sH[i];  // enc_h
    }
}

// =====================================================================
// K3: logits = dec_hs @ outW^T + outB. Tile 64(t) x 128(v), 256 thr,
// acc[4][8], cp.async double-buffer, 2 CTAs/SM. Fused softmax partials.
// grid (NVT, 8). Logits never hit HBM.
// =====================================================================
__global__ __launch_bounds__(256, 2) void logits_kernel(
    const float* __restrict__ outW, const float* __restrict__ outB,
    const int* __restrict__ target)
{
    const int t0 = blockIdx.y * 64;
    const int v0 = blockIdx.x * 128;

    __shared__ __align__(16) unsigned long long As[2][10][64];   // 10 KB
    __shared__ __align__(16) unsigned long long Bs[2][10][128];  // 20 KB
    __shared__ float sOb[128];
    __shared__ float sRowMax[64];
    __shared__ int   sRowIdx[64];

    const int tid = threadIdx.x;
    if (tid < 128) {
        int v = v0 + tid;
        sOb[tid] = (v < VOC) ? outB[v] : 0.f;
    }

    unsigned long long acc[4][8];
#pragma unroll
    for (int i = 0; i < 4; i++)
#pragma unroll
        for (int m = 0; m < 8; m++) acc[i][m] = 0ull;

    const int ty = tid >> 4, tx = tid & 15;

    // ---- cp.async chunk issue ----
    #define ISSUE_CHUNK(KC, BUF) do {                                        \
        const int kb_ = (KC) * 20;                                           \
        _Pragma("unroll")                                                    \
        for (int r_ = 0; r_ < 8; r_++) {                                     \
            int id_ = tid + (r_ << 8);                                       \
            if (id_ < 640) {                                                 \
                int k2_ = id_ >> 6, col_ = id_ & 63;                         \
                const float* src_ = gDecHs + (size_t)(t0 + col_) * HID + kb_ + k2_ * 2; \
                CP_ASYNC8(smem_u32(&As[BUF][k2_][col_]), src_, 8);           \
            } else if (id_ < 1920) {                                         \
                int e_ = id_ - 640;                                          \
                int k2_ = e_ >> 7, col_ = e_ & 127;                          \
                int v_ = v0 + col_;                                          \
                const float* src_ = outW + (size_t)(v_ < VOC ? v_ : 0) * HID + kb_ + k2_ * 2; \
                CP_ASYNC8(smem_u32(&Bs[BUF][k2_][col_]), src_, (v_ < VOC) ? 8 : 0); \
            }                                                                \
        }                                                                    \
        CP_COMMIT();                                                         \
    } while (0)

    ISSUE_CHUNK(0, 0);
    ISSUE_CHUNK(1, 1);

    for (int kc = 0; kc < 25; kc++) {
        const int cur = kc & 1;
        if (kc < 24) asm volatile("cp.async.wait_group 1;" ::: "memory");
        else         asm volatile("cp.async.wait_group 0;" ::: "memory");
        __syncthreads();

#pragma unroll
        for (int k2 = 0; k2 < 10; k2++) {
            unsigned long long a[4], b[8];
            const ulonglong2* ap = (const ulonglong2*)&As[cur][k2][ty << 2];
            ulonglong2 q;
            q = ap[0]; a[0] = q.x; a[1] = q.y;
            q = ap[1]; a[2] = q.x; a[3] = q.y;
#pragma unroll
            for (int m = 0; m < 8; m++) b[m] = Bs[cur][k2][tx + (m << 4)];
#pragma unroll
            for (int i = 0; i < 4; i++)
#pragma unroll
                for (int m = 0; m < 8; m++) ffma2(acc[i][m], a[i], b[m]);
        }
        __syncthreads();
        if (kc + 2 < 25) ISSUE_CHUNK(kc + 2, cur);
    }

    // ---- fused epilogue: per-(row, vtile) max / argmax / sum-exp ----
    float* sM = (float*)As;                 // 64*16 floats, fits
    int*   sI = (int*)Bs;

#pragma unroll
    for (int i = 0; i < 4; i++) {
        int row = (ty << 2) + i;
        int t = t0 + row;
        int tgt = target[t];
        float lmax = -1e30f; int lidx = 0;
#pragma unroll
        for (int m = 0; m < 8; m++) {
            int v = v0 + tx + (m << 4);
            if (v < VOC) {
                float x, y; ull2f2(acc[i][m], x, y);
                float logit = x + y + sOb[tx + (m << 4)];
                if (logit > lmax) { lmax = logit; lidx = v; }
                if (v == tgt) gTlogit[t] = logit;
            }
        }
        sM[row * 16 + tx] = lmax;
        sI[row * 16 + tx] = lidx;
    }
    __syncthreads();

    if (tid < 64) {
        float m = -1e30f; int idx = 0x7fffffff;
        for (int e = 0; e < 16; e++) {
            float me = sM[tid * 16 + e]; int ie = sI[tid * 16 + e];
            if (me > m || (me == m && ie < idx)) { m = me; idx = ie; }
        }
        sRowMax[tid] = m; sRowIdx[tid] = idx;
    }
    __syncthreads();

    float* sS = (float*)As;
#pragma unroll
    for (int i = 0; i < 4; i++) {
        int row = (ty << 2) + i;
        float rmax = sRowMax[row];
        float lsum = 0.f;
#pragma unroll
        for (int m = 0; m < 8; m++) {
            int v = v0 + tx + (m << 4);
            if (v < VOC) {
                float x, y; ull2f2(acc[i][m], x, y);
                lsum += __expf(x + y + sOb[tx + (m << 4)] - rmax);
            }
        }
        sS[row * 16 + tx] = lsum;
    }
    __syncthreads();

    if (tid < 64) {
        float s = 0.f;
        for (int e = 0; e < 16; e++) s += sS[tid * 16 + e];
        int t = t0 + tid;
        size_t o = (size_t)t * NVT + blockIdx.x;
        gPmax[o] = sRowMax[tid];
        gPidx[o] = sRowIdx[tid];
        gPsum[o] = s;
    }
}

// =====================================================================
// K4: per-row cross-tile reduction -> argmax + NLL.   grid(512) x 128
// =====================================================================
__global__ __launch_bounds__(128) void finalize_kernel(float* __restrict__ dOut)
{
    const int t = blockIdx.x;
    const int tid = threadIdx.x;
    __shared__ float rm[128];
    __shared__ int   ri[128];
    __shared__ float rs[128];

    float m = -1e30f; int idx = 0x7fffffff;
    for (int vt = tid; vt < NVT; vt += 128) {
        float mv = gPmax[(size_t)t * NVT + vt];
        int   iv = gPidx[(size_t)t * NVT + vt];
        if (mv > m || (mv == m && iv < idx)) { m = mv; idx = iv; }
    }
    rm[tid] = m; ri[tid] = idx;
    __syncthreads();
    for (int off = 64; off; off >>= 1) {
        if (tid < off) {
            float m2 = rm[tid + off]; int i2 = ri[tid + off];
            if (m2 > rm[tid] || (m2 == rm[tid] && i2 < ri[tid])) { rm[tid] = m2; ri[tid] = i2; }
        }
        __syncthreads();
    }
    float gmax = rm[0]; int gidx = ri[0];

    float s = 0.f;
    for (int vt = tid; vt < NVT; vt += 128) {
        size_t o = (size_t)t * NVT + vt;
        s += gPsum[o] * expf(gPmax[o] - gmax);
    }
    rs[tid] = s;
    __syncthreads();
    for (int off = 64; off; off >>= 1) {
        if (tid < off) rs[tid] += rs[tid + off];
        __syncthreads();
    }
    if (tid == 0) {
        float lse = gmax + logf(rs[0]);
        gNll[t] = lse - gTlogit[t];
        dOut[1 + HID + t] = (float)gidx;     // decoder_outputs
    }
}

// =====================================================================
// K5: loss = sum(gNll).   1 block x 512
// =====================================================================
__global__ __launch_bounds__(512) void loss_kernel(float* __restrict__ dOut)
{
    __shared__ float rs[512];
    int tid = threadIdx.x;
    rs[tid] = gNll[tid];
    __syncthreads();
    for (int off = 256; off; off >>= 1) {
        if (tid < off) rs[tid] += rs[tid + off];
        __syncthreads();
    }
    if (tid == 0) dOut[0] = rs[0];
}

// =====================================================================
extern "C" void kernel_launch(void* const* d_in, const int* in_sizes, int n_in,
                              void* d_out, int out_size)
{
    const int*   encTok = (const int*)d_in[0];
    const int*   tgtTok = (const int*)d_in[1];
    const float* encH0  = (const float*)d_in[2];
    const float* encEmb = (const float*)d_in[3];
    const float* encWih = (const float*)d_in[4];
    const float* encWhh = (const float*)d_in[5];
    const float* encBih = (const float*)d_in[6];
    const float* encBhh = (const float*)d_in[7];
    const float* decEmb = (const float*)d_in[8];
    const float* decWih = (const float*)d_in[9];
    const float* decWhh = (const float*)d_in[10];
    const float* decBih = (const float*)d_in[11];
    const float* decBhh = (const float*)d_in[12];
    const float* outW   = (const float*)d_in[13];
    const float* outB   = (const float*)d_in[14];
    float* out = (float*)d_out;

    reset_kernel<<<2, 800>>>();
    gi_gemm_kernel<<<dim3(12, 4, 2), 256>>>(encTok, tgtTok, encEmb, decEmb,
                                            encWih, decWih, encBih, decBih);
    gru_rec_kernel<<<RBLK, 672>>>(encWhh, encBhh, encH0, out, 0, 0u);
    gru_rec_kernel<<<RBLK, 672>>>(decWhh, decBhh, encH0, out, 1, 512u);
    logits_kernel<<<dim3(NVT, 8), 256>>>(outW, outB, tgtTok);
    finalize_kernel<<<512, 128>>>(out);
    loss_kernel<<<1, 512>>>(out);
}

// round 13
// speedup vs baseline: 1.1858x; 1.1858x over previous
#include <cuda_runtime.h>
#include <cuda_bf16.h>

#define S_LEN 512
#define HID   500
#define G3    1500
#define VOC   50000
#define NVT   391          // ceil(50000/128)
#define RBLK  25           // recurrence blocks
#define RWPB  20           // warps per recurrence block (25*20 = 500 = HID)

// ---------------- static device scratch ----------------
__device__ float gGiEnc[S_LEN * G3];
__device__ float gGiDec[S_LEN * G3];
// mailbox lines: [parity][block] = 128B line: 20 h floats + flag word at [31]
__device__ __align__(128) float gHx[2][RBLK][32];
__device__ __align__(16) float gHfinal[512];
__device__ float gDecHs[S_LEN * HID];
__device__ float gPmax[S_LEN * NVT];
__device__ float gPsum[S_LEN * NVT];
__device__ int   gPidx[S_LEN * NVT];
__device__ float gTlogit[S_LEN];
__device__ float gNll[S_LEN];

// ---------------- helpers ----------------
__device__ __forceinline__ unsigned long long f22ull(float x, float y) {
    unsigned long long u;
    asm("mov.b64 %0, {%1, %2};" : "=l"(u) : "f"(x), "f"(y));
    return u;
}
__device__ __forceinline__ void ull2f2(unsigned long long u, float& x, float& y) {
    asm("mov.b64 {%0, %1}, %2;" : "=f"(x), "=f"(y) : "l"(u));
}
__device__ __forceinline__ void ffma2(unsigned long long& d, unsigned long long a, unsigned long long b) {
    asm("fma.rn.f32x2 %0, %1, %2, %0;" : "+l"(d) : "l"(a), "l"(b));
}
__device__ __forceinline__ unsigned ld_acq(const unsigned* p) {
    unsigned v;
    asm volatile("ld.acquire.gpu.global.u32 %0, [%1];" : "=r"(v) : "l"(p) : "memory");
    return v;
}
__device__ __forceinline__ void st_rel(unsigned* p, unsigned v) {
    asm volatile("st.release.gpu.global.u32 [%0], %1;" :: "l"(p), "r"(v) : "memory");
}
__device__ __forceinline__ float sigmoid_fast(float x) {
    return __fdividef(1.f, 1.f + __expf(-x));
}
__device__ __forceinline__ float tanh_fast(float x) {
    return __fdividef(2.f, 1.f + __expf(-2.f * x)) - 1.f;
}

// =====================================================================
// K0: reset mailbox flags/data (replay safety).
// =====================================================================
__global__ void reset_kernel() {
    int i = blockIdx.x * blockDim.x + threadIdx.x;
    if (i < 2 * RBLK * 32) ((float*)gHx)[i] = 0.f;
}

// =====================================================================
// K1: gi = gather(emb, tok)[relu if dec] @ Wih^T + bih   for enc & dec
// grid (12, 4, 2). Conflict-free B fragments: thread tx owns cols tx+16m.
// =====================================================================
__global__ __launch_bounds__(256, 1) void gi_gemm_kernel(
    const int* __restrict__ encTok, const int* __restrict__ tgtTok,
    const float* __restrict__ encEmb, const float* __restrict__ decEmb,
    const float* __restrict__ encWih, const float* __restrict__ decWih,
    const float* __restrict__ encBih, const float* __restrict__ decBih)
{
    const int mode = blockIdx.z;
    const float* emb  = mode ? decEmb : encEmb;
    const float* W    = mode ? decWih : encWih;
    const float* bias = mode ? decBih : encBih;
    float* out = mode ? gGiDec : gGiEnc;

    const int t0 = blockIdx.y * 128;
    const int g0 = blockIdx.x * 128;

    __shared__ __align__(16) unsigned long long As[10][128];
    __shared__ __align__(16) unsigned long long Bs[10][128];
    __shared__ int   sTok[128];
    __shared__ float sBias[128];

    const int tid = threadIdx.x;
    if (tid < 128) {
        int t = t0 + tid;
        int tok;
        if (mode) tok = (t == 0) ? 0 : tgtTok[t - 1];   // teacher forcing, PAD first
        else      tok = encTok[t];
        sTok[tid] = tok;
        int g = g0 + tid;
        sBias[tid] = (g < G3) ? bias[g] : 0.f;
    }
    __syncthreads();

    unsigned long long acc[8][8];
#pragma unroll
    for (int i = 0; i < 8; i++)
#pragma unroll
        for (int j = 0; j < 8; j++) acc[i][j] = 0ull;

    const int ty = tid >> 4, tx = tid & 15;

    for (int kc = 0; kc < 25; kc++) {
        const int kb = kc * 20;
#pragma unroll
        for (int r = 0; r < 5; r++) {
            int id  = tid + r * 256;
            int k2  = id >> 7;
            int col = id & 127;
            const float* ap = emb + (size_t)sTok[col] * HID + kb + k2 * 2;
            float2 av = *(const float2*)ap;
            if (mode) { av.x = fmaxf(av.x, 0.f); av.y = fmaxf(av.y, 0.f); }
            As[k2][col] = f22ull(av.x, av.y);
            int g = g0 + col;
            float2 bv = make_float2(0.f, 0.f);
            if (g < G3) bv = *(const float2*)(W + (size_t)g * HID + kb + k2 * 2);
            Bs[k2][col] = f22ull(bv.x, bv.y);
        }
        __syncthreads();
#pragma unroll
        for (int k2 = 0; k2 < 10; k2++) {
            unsigned long long a[8], b[8];
            const ulonglong2* ap = (const ulonglong2*)&As[k2][ty << 3];
            ulonglong2 q;
            q = ap[0]; a[0] = q.x; a[1] = q.y;
            q = ap[1]; a[2] = q.x; a[3] = q.y;
            q = ap[2]; a[4] = q.x; a[5] = q.y;
            q = ap[3]; a[6] = q.x; a[7] = q.y;
#pragma unroll
            for (int m = 0; m < 8; m++) b[m] = Bs[k2][tx + (m << 4)];
#pragma unroll
            for (int i = 0; i < 8; i++)
#pragma unroll
                for (int j = 0; j < 8; j++) ffma2(acc[i][j], a[i], b[j]);
        }
        __syncthreads();
    }

#pragma unroll
    for (int i = 0; i < 8; i++) {
        int t = t0 + (ty << 3) + i;
#pragma unroll
        for (int m = 0; m < 8; m++) {
            int g = g0 + tx + (m << 4);
            if (g < G3) {
                float x, y; ull2f2(acc[i][m], x, y);
                out[(size_t)t * G3 + g] = x + y + sBias[tx + (m << 4)];
            }
        }
    }
}

// =====================================================================
// K2: GRU recurrence, persistent. 25 blocks x 640 threads (R10 structure,
// compute path tightened: f32x2 matvec, MUFU activations, decHs after flag).
// =====================================================================
__global__ __launch_bounds__(640, 1) void gru_rec_kernel(
    const float* __restrict__ Whh, const float* __restrict__ bhh,
    const float* __restrict__ h0_in, float* __restrict__ dOut,
    int mode, unsigned flagBase)
{
    const float* gi = mode ? gGiDec : gGiEnc;
    const int tid  = threadIdx.x;
    const int warp = tid >> 5;
    const int lane = tid & 31;
    const int j = blockIdx.x * RWPB + warp;   // 0..499

    __shared__ __align__(16) float sH[512];
    __shared__ __align__(16) float sStage[RWPB];

    // packed weights: ull i holds the (k, k+1) pair
    unsigned long long wr2[8], wz2[8], wn2[8];
#pragma unroll
    for (int i = 0; i < 4; i++) {
        int kb = (i << 7) + (lane << 2);
        float4 a = make_float4(0.f,0.f,0.f,0.f), b = a, c = a;
        if (kb + 3 < HID) {
            a = *(const float4*)(Whh + (size_t)j * HID + kb);
            b = *(const float4*)(Whh + (size_t)(j + HID) * HID + kb);
            c = *(const float4*)(Whh + (size_t)(j + 2 * HID) * HID + kb);
        }
        wr2[i*2+0] = f22ull(a.x, a.y); wr2[i*2+1] = f22ull(a.z, a.w);
        wz2[i*2+0] = f22ull(b.x, b.y); wz2[i*2+1] = f22ull(b.z, b.w);
        wn2[i*2+0] = f22ull(c.x, c.y); wn2[i*2+1] = f22ull(c.z, c.w);
    }
    const float br = bhh[j], bz = bhh[j + HID], bn = bhh[j + 2 * HID];

    // init sH from h0 (enc) / gHfinal (dec); pad 500..511 with zeros
    if (tid < 128) {
        float4 v = make_float4(0.f, 0.f, 0.f, 0.f);
        if (tid < 125) {
            if (mode) v = *(const float4*)(gHfinal + tid * 4);
            else      v = *(const float4*)(h0_in + tid * 4);
        }
        *(float4*)(sH + tid * 4) = v;
    }

    // prefetch gi for step 0
    float gir = 0.f, giz = 0.f, gin = 0.f;
    if (lane == 0) {
        const float* g0 = gi + j;
        gir = g0[0]; giz = g0[HID]; gin = g0[2 * HID];
    }
    __syncthreads();

    for (int s = 0; s < S_LEN; s++) {
        // ---- compute: packed h from shared, packed matvec ----
        unsigned long long h2[8];
#pragma unroll
        for (int i = 0; i < 4; i++) {
            ulonglong2 q = *(const ulonglong2*)(sH + (i << 7) + (lane << 2));
            h2[i*2] = q.x; h2[i*2+1] = q.y;
        }
        float hold = 0.f;
        if (lane == 0) hold = sH[j];

        unsigned long long aR = 0ull, aZ = 0ull, aN = 0ull;
#pragma unroll
        for (int i = 0; i < 8; i++) {
            ffma2(aR, wr2[i], h2[i]);
            ffma2(aZ, wz2[i], h2[i]);
            ffma2(aN, wn2[i], h2[i]);
        }
        float x, y;
        ull2f2(aR, x, y); float ar = x + y;
        ull2f2(aZ, x, y); float az = x + y;
        ull2f2(aN, x, y); float an = x + y;
#pragma unroll
        for (int off = 16; off; off >>= 1) {
            ar += __shfl_xor_sync(0xffffffffu, ar, off);
            az += __shfl_xor_sync(0xffffffffu, az, off);
            an += __shfl_xor_sync(0xffffffffu, an, off);
        }
        if (lane == 0) {
            float r = sigmoid_fast(gir + ar + br);
            float z = sigmoid_fast(giz + az + bz);
            float n = tanh_fast(gin + r * (an + bn));
            sStage[warp] = (1.f - z) * n + z * hold;
            if (s + 1 < S_LEN) {           // prefetch next gi — hides under exchange
                const float* gs = gi + (size_t)(s + 1) * G3 + j;
                gir = gs[0]; giz = gs[HID]; gin = gs[2 * HID];
            }
        }
        __syncthreads();                   // A: sStage complete, sH reads done

        const unsigned want = flagBase + 1u + (unsigned)s;
        if (warp == 0) {
            // ---- produce: one 128B mailbox line (data + release flag) ----
            if (lane == 0) {
                float* line = gHx[s & 1][blockIdx.x];
                float4 d0 = *(const float4*)(sStage + 0);
                float4 d1 = *(const float4*)(sStage + 4);
                float4 d2 = *(const float4*)(sStage + 8);
                float4 d3 = *(const float4*)(sStage + 12);
                float4 d4 = *(const float4*)(sStage + 16);
                __stcg((float4*)line + 0, d0);
                __stcg((float4*)line + 1, d1);
                __stcg((float4*)line + 2, d2);
                __stcg((float4*)line + 3, d3);
                __stcg((float4*)line + 4, d4);
                st_rel((unsigned*)(line + 31), want);   // orders mailbox stores
                if (mode) {                // AFTER flag: ordered by kernel boundary
                    float4* hp = (float4*)(gDecHs + (size_t)s * HID + blockIdx.x * RWPB);
                    __stcg(hp + 0, d0); __stcg(hp + 1, d1); __stcg(hp + 2, d2);
                    __stcg(hp + 3, d3); __stcg(hp + 4, d4);
                }
            }
            // ---- consume: lane b polls block b's flag, pulls same line ----
            if (lane < RBLK) {
                const float* line = gHx[s & 1][lane];
                const unsigned* fp = (const unsigned*)(line + 31);
                while (ld_acq(fp) < want) { }
                float4 v0 = __ldcg((const float4*)line + 0);
                float4 v1 = __ldcg((const float4*)line + 1);
                float4 v2 = __ldcg((const float4*)line + 2);
                float4 v3 = __ldcg((const float4*)line + 3);
                float4 v4 = __ldcg((const float4*)line + 4);
                float* dst = sH + lane * RWPB;
                *(float4*)(dst + 0)  = v0;
                *(float4*)(dst + 4)  = v1;
                *(float4*)(dst + 8)  = v2;
                *(float4*)(dst + 12) = v3;
                *(float4*)(dst + 16) = v4;
            }
        }
        __syncthreads();                   // B: sH holds step-s result
    }

    if (!mode && blockIdx.x == 0) {
        if (tid < 512) gHfinal[tid] = sH[tid];
        if (tid < HID) dOut[1 + tid] = sH[tid];   // enc_h output slice
    }
}

// =====================================================================
// K3: logits = dec_hs @ outW^T + outB. 512 threads, tile 128x128,
// acc[4][8], register-staged double buffer (proven), 4 warps/SMSP.
// B fragments paired: thread tx owns cols 2tx+32p+{0,1} -> LDS.128.
// Fused per-tile softmax partials. grid (NVT, 4). Logits never hit HBM.
// =====================================================================
__global__ __launch_bounds__(512, 1) void logits_kernel(
    const float* __restrict__ outW, const float* __restrict__ outB,
    const int* __restrict__ target)
{
    const int t0 = blockIdx.y * 128;
    const int v0 = blockIdx.x * 128;

    __shared__ __align__(16) unsigned long long As[2][10][128];  // 20 KB
    __shared__ __align__(16) unsigned long long Bs[2][10][128];  // 20 KB
    __shared__ float sOb[128];
    __shared__ float sRowMax[128];
    __shared__ int   sRowIdx[128];

    const int tid = threadIdx.x;
    if (tid < 128) {
        int v = v0 + tid;
        sOb[tid] = (v < VOC) ? outB[v] : 0.f;
    }

    unsigned long long acc[4][8];
#pragma unroll
    for (int i = 0; i < 4; i++)
#pragma unroll
        for (int m = 0; m < 8; m++) acc[i][m] = 0ull;

    const int ty = tid >> 4, tx = tid & 15;   // ty 0..31 (4 rows each), tx 0..15

    // prologue: chunk 0 into buffer 0 (2560 ull / 512 thr = 5 each)
    {
#pragma unroll
        for (int r = 0; r < 5; r++) {
            int id = tid + r * 512;
            if (id < 1280) {
                int k2 = id >> 7, col = id & 127;
                float2 av = *(const float2*)(gDecHs + (size_t)(t0 + col) * HID + k2 * 2);
                As[0][k2][col] = f22ull(av.x, av.y);
            } else {
                int e = id - 1280;
                int k2 = e >> 7, col = e & 127;
                int v = v0 + col;
                float2 bv = make_float2(0.f, 0.f);
                if (v < VOC) bv = *(const float2*)(outW + (size_t)v * HID + k2 * 2);
                Bs[0][k2][col] = f22ull(bv.x, bv.y);
            }
        }
    }
    __syncthreads();

    for (int kc = 0; kc < 25; kc++) {
        const int cur = kc & 1, nxt = cur ^ 1;

        unsigned long long st[5];
        if (kc < 24) {
            const int kb = (kc + 1) * 20;
#pragma unroll
            for (int r = 0; r < 5; r++) {
                int id = tid + r * 512;
                if (id < 1280) {
                    int k2 = id >> 7, col = id & 127;
                    float2 av = *(const float2*)(gDecHs + (size_t)(t0 + col) * HID + kb + k2 * 2);
                    st[r] = f22ull(av.x, av.y);
                } else {
                    int e = id - 1280;
                    int k2 = e >> 7, col = e & 127;
                    int v = v0 + col;
                    float2 bv = make_float2(0.f, 0.f);
                    if (v < VOC) bv = *(const float2*)(outW + (size_t)v * HID + kb + k2 * 2);
                    st[r] = f22ull(bv.x, bv.y);
                }
            }
        }

#pragma unroll
        for (int k2 = 0; k2 < 10; k2++) {
            unsigned long long a[4], b[8];
            ulonglong2 q;
            const ulonglong2* ap = (const ulonglong2*)&As[cur][k2][ty << 2];
            q = ap[0]; a[0] = q.x; a[1] = q.y;
            q = ap[1]; a[2] = q.x; a[3] = q.y;
#pragma unroll
            for (int p = 0; p < 4; p++) {
                q = *(const ulonglong2*)&Bs[cur][k2][(tx << 1) + (p << 5)];
                b[p*2] = q.x; b[p*2+1] = q.y;
            }
#pragma unroll
            for (int i = 0; i < 4; i++)
#pragma unroll
                for (int m = 0; m < 8; m++) ffma2(acc[i][m], a[i], b[m]);
        }

        if (kc < 24) {
#pragma unroll
            for (int r = 0; r < 5; r++) {
                int id = tid + r * 512;
                if (id < 1280) {
                    int k2 = id >> 7, col = id & 127;
                    As[nxt][k2][col] = st[r];
                } else {
                    int e = id - 1280;
                    int k2 = e >> 7, col = e & 127;
                    Bs[nxt][k2][col] = st[r];
                }
            }
        }
        __syncthreads();
    }

    // col(m) = 2tx + 32*(m>>1) + (m&1)
    // ---- fused epilogue: per-(row, vtile) max / argmax / sum-exp ----
    float* sM = (float*)As;
    int*   sI = (int*)Bs;

#pragma unroll
    for (int i = 0; i < 4; i++) {
        int row = (ty << 2) + i;
        int t = t0 + row;
        int tgt = target[t];
        float lmax = -1e30f; int lidx = 0;
#pragma unroll
        for (int m = 0; m < 8; m++) {
            int col = (tx << 1) + ((m >> 1) << 5) + (m & 1);
            int v = v0 + col;
            if (v < VOC) {
                float x, y; ull2f2(acc[i][m], x, y);
                float logit = x + y + sOb[col];
                if (logit > lmax) { lmax = logit; lidx = v; }
                if (v == tgt) gTlogit[t] = logit;
            }
        }
        sM[row * 16 + tx] = lmax;
        sI[row * 16 + tx] = lidx;
    }
    __syncthreads();

    if (tid < 128) {
        float m = -1e30f; int idx = 0x7fffffff;
        for (int e = 0; e < 16; e++) {
            float me = sM[tid * 16 + e]; int ie = sI[tid * 16 + e];
            if (me > m || (me == m && ie < idx)) { m = me; idx = ie; }
        }
        sRowMax[tid] = m; sRowIdx[tid] = idx;
    }
    __syncthreads();

    float* sS = (float*)Bs;                 // As holds sM still? reuse Bs for sums
#pragma unroll
    for (int i = 0; i < 4; i++) {
        int row = (ty << 2) + i;
        float rmax = sRowMax[row];
        float lsum = 0.f;
#pragma unroll
        for (int m = 0; m < 8; m++) {
            int col = (tx << 1) + ((m >> 1) << 5) + (m & 1);
            int v = v0 + col;
            if (v < VOC) {
                float x, y; ull2f2(acc[i][m], x, y);
                lsum += __expf(x + y + sOb[col] - rmax);
            }
        }
        sS[row * 16 + tx] = lsum;
    }
    __syncthreads();

    if (tid < 128) {
        float s = 0.f;
        for (int e = 0; e < 16; e++) s += sS[tid * 16 + e];
        int t = t0 + tid;
        size_t o = (size_t)t * NVT + blockIdx.x;
        gPmax[o] = sRowMax[tid];
        gPidx[o] = sRowIdx[tid];
        gPsum[o] = s;
    }
}

// =====================================================================
// K4: per-row cross-tile reduction -> argmax + NLL.   grid(512) x 128
// =====================================================================
__global__ __launch_bounds__(128) void finalize_kernel(float* __restrict__ dOut)
{
    const int t = blockIdx.x;
    const int tid = threadIdx.x;
    __shared__ float rm[128];
    __shared__ int   ri[128];
    __shared__ float rs[128];

    float m = -1e30f; int idx = 0x7fffffff;
    for (int vt = tid; vt < NVT; vt += 128) {
        float mv = gPmax[(size_t)t * NVT + vt];
        int   iv = gPidx[(size_t)t * NVT + vt];
        if (mv > m || (mv == m && iv < idx)) { m = mv; idx = iv; }
    }
    rm[tid] = m; ri[tid] = idx;
    __syncthreads();
    for (int off = 64; off; off >>= 1) {
        if (tid < off) {
            float m2 = rm[tid + off]; int i2 = ri[tid + off];
            if (m2 > rm[tid] || (m2 == rm[tid] && i2 < ri[tid])) { rm[tid] = m2; ri[tid] = i2; }
        }
        __syncthreads();
    }
    float gmax = rm[0]; int gidx = ri[0];

    float s = 0.f;
    for (int vt = tid; vt < NVT; vt += 128) {
        size_t o = (size_t)t * NVT + vt;
        s += gPsum[o] * expf(gPmax[o] - gmax);
    }
    rs[tid] = s;
    __syncthreads();
    for (int off = 64; off; off >>= 1) {
        if (tid < off) rs[tid] += rs[tid + off];
        __syncthreads();
    }
    if (tid == 0) {
        float lse = gmax + logf(rs[0]);
        gNll[t] = lse - gTlogit[t];
        dOut[1 + HID + t] = (float)gidx;     // decoder_outputs
    }
}

// =====================================================================
// K5: loss = sum(gNll).   1 block x 512
// =====================================================================
__global__ __launch_bounds__(512) void loss_kernel(float* __restrict__ dOut)
{
    __shared__ float rs[512];
    int tid = threadIdx.x;
    rs[tid] = gNll[tid];
    __syncthreads();
    for (int off = 256; off; off >>= 1) {
        if (tid < off) rs[tid] += rs[tid + off];
        __syncthreads();
    }
    if (tid == 0) dOut[0] = rs[0];
}

// =====================================================================
extern "C" void kernel_launch(void* const* d_in, const int* in_sizes, int n_in,
                              void* d_out, int out_size)
{
    const int*   encTok = (const int*)d_in[0];
    const int*   tgtTok = (const int*)d_in[1];
    const float* encH0  = (const float*)d_in[2];
    const float* encEmb = (const float*)d_in[3];
    const float* encWih = (const float*)d_in[4];
    const float* encWhh = (const float*)d_in[5];
    const float* encBih = (const float*)d_in[6];
    const float* encBhh = (const float*)d_in[7];
    const float* decEmb = (const float*)d_in[8];
    const float* decWih = (const float*)d_in[9];
    const float* decWhh = (const float*)d_in[10];
    const float* decBih = (const float*)d_in[11];
    const float* decBhh = (const float*)d_in[12];
    const float* outW   = (const float*)d_in[13];
    const float* outB   = (const float*)d_in[14];
    float* out = (float*)d_out;

    reset_kernel<<<2, 800>>>();
    gi_gemm_kernel<<<dim3(12, 4, 2), 256>>>(encTok, tgtTok, encEmb, decEmb,
                                            encWih, decWih, encBih, decBih);
    gru_rec_kernel<<<RBLK, 640>>>(encWhh, encBhh, encH0, out, 0, 0u);
    gru_rec_kernel<<<RBLK, 640>>>(decWhh, decBhh, encH0, out, 1, 512u);
    logits_kernel<<<dim3(NVT, 4), 512>>>(outW, outB, tgtTok);
    finalize_kernel<<<512, 128>>>(out);
    loss_kernel<<<1, 512>>>(out);
}

// round 14
// speedup vs baseline: 1.7405x; 1.4678x over previous
#include <cuda_runtime.h>
#include <cuda_bf16.h>

#define S_LEN 512
#define HID   500
#define G3    1500
#define VOC   50000
#define NVT   391          // ceil(50000/128)
#define RBLK  25           // fallback recurrence blocks
#define RWPB  20           // fallback warps per block
#define CLN   16           // cluster size for DSMEM recurrence

// ---------------- static device scratch ----------------
__device__ float gGiEnc[S_LEN * G3];
__device__ float gGiDec[S_LEN * G3];
// fallback mailbox lines: [parity][block] = 128B line: 20 floats + flag [31]
__device__ __align__(128) float gHx[2][RBLK][32];
__device__ __align__(16) float gHfinal[512];
__device__ float gDecHs[S_LEN * HID];
__device__ float gPmax[S_LEN * NVT];
__device__ float gPsum[S_LEN * NVT];
__device__ int   gPidx[S_LEN * NVT];
__device__ float gTlogit[S_LEN];
__device__ float gNll[S_LEN];

// ---------------- helpers ----------------
__device__ __forceinline__ unsigned long long f22ull(float x, float y) {
    unsigned long long u;
    asm("mov.b64 %0, {%1, %2};" : "=l"(u) : "f"(x), "f"(y));
    return u;
}
__device__ __forceinline__ void ull2f2(unsigned long long u, float& x, float& y) {
    asm("mov.b64 {%0, %1}, %2;" : "=f"(x), "=f"(y) : "l"(u));
}
__device__ __forceinline__ void ffma2(unsigned long long& d, unsigned long long a, unsigned long long b) {
    asm("fma.rn.f32x2 %0, %1, %2, %0;" : "+l"(d) : "l"(a), "l"(b));
}
__device__ __forceinline__ unsigned ld_acq(const unsigned* p) {
    unsigned v;
    asm volatile("ld.acquire.gpu.global.u32 %0, [%1];" : "=r"(v) : "l"(p) : "memory");
    return v;
}
__device__ __forceinline__ void st_rel(unsigned* p, unsigned v) {
    asm volatile("st.release.gpu.global.u32 [%0], %1;" :: "l"(p), "r"(v) : "memory");
}
__device__ __forceinline__ float sigmoid_fast(float x) {
    return __fdividef(1.f, 1.f + __expf(-x));
}
__device__ __forceinline__ float tanh_fast(float x) {
    return __fdividef(2.f, 1.f + __expf(-2.f * x)) - 1.f;
}
__device__ __forceinline__ unsigned smem_u32(const void* p) {
    return (unsigned)__cvta_generic_to_shared(p);
}
__device__ __forceinline__ unsigned cluster_rank() {
    unsigned r; asm("mov.u32 %0, %%cluster_ctarank;" : "=r"(r)); return r;
}
__device__ __forceinline__ unsigned mapa_cta(unsigned saddr, unsigned rank) {
    unsigned r;
    asm("mapa.shared::cluster.u32 %0, %1, %2;" : "=r"(r) : "r"(saddr), "r"(rank));
    return r;
}
#define CLUSTER_ARRIVE() asm volatile("barrier.cluster.arrive.aligned;" ::: "memory")
#define CLUSTER_WAIT()   asm volatile("barrier.cluster.wait.aligned;" ::: "memory")

// =====================================================================
// K0: reset fallback mailbox (only used on fallback path; cheap anyway)
// =====================================================================
__global__ void reset_kernel() {
    int i = blockIdx.x * blockDim.x + threadIdx.x;
    if (i < 2 * RBLK * 32) ((float*)gHx)[i] = 0.f;
}

// =====================================================================
// K1: gi = gather(emb, tok)[relu if dec] @ Wih^T + bih   for enc & dec
// =====================================================================
__global__ __launch_bounds__(256, 1) void gi_gemm_kernel(
    const int* __restrict__ encTok, const int* __restrict__ tgtTok,
    const float* __restrict__ encEmb, const float* __restrict__ decEmb,
    const float* __restrict__ encWih, const float* __restrict__ decWih,
    const float* __restrict__ encBih, const float* __restrict__ decBih)
{
    const int mode = blockIdx.z;
    const float* emb  = mode ? decEmb : encEmb;
    const float* W    = mode ? decWih : encWih;
    const float* bias = mode ? decBih : encBih;
    float* out = mode ? gGiDec : gGiEnc;

    const int t0 = blockIdx.y * 128;
    const int g0 = blockIdx.x * 128;

    __shared__ __align__(16) unsigned long long As[10][128];
    __shared__ __align__(16) unsigned long long Bs[10][128];
    __shared__ int   sTok[128];
    __shared__ float sBias[128];

    const int tid = threadIdx.x;
    if (tid < 128) {
        int t = t0 + tid;
        int tok;
        if (mode) tok = (t == 0) ? 0 : tgtTok[t - 1];
        else      tok = encTok[t];
        sTok[tid] = tok;
        int g = g0 + tid;
        sBias[tid] = (g < G3) ? bias[g] : 0.f;
    }
    __syncthreads();

    unsigned long long acc[8][8];
#pragma unroll
    for (int i = 0; i < 8; i++)
#pragma unroll
        for (int j = 0; j < 8; j++) acc[i][j] = 0ull;

    const int ty = tid >> 4, tx = tid & 15;

    for (int kc = 0; kc < 25; kc++) {
        const int kb = kc * 20;
#pragma unroll
        for (int r = 0; r < 5; r++) {
            int id  = tid + r * 256;
            int k2  = id >> 7;
            int col = id & 127;
            const float* ap = emb + (size_t)sTok[col] * HID + kb + k2 * 2;
            float2 av = *(const float2*)ap;
            if (mode) { av.x = fmaxf(av.x, 0.f); av.y = fmaxf(av.y, 0.f); }
            As[k2][col] = f22ull(av.x, av.y);
            int g = g0 + col;
            float2 bv = make_float2(0.f, 0.f);
            if (g < G3) bv = *(const float2*)(W + (size_t)g * HID + kb + k2 * 2);
            Bs[k2][col] = f22ull(bv.x, bv.y);
        }
        __syncthreads();
#pragma unroll
        for (int k2 = 0; k2 < 10; k2++) {
            unsigned long long a[8], b[8];
            const ulonglong2* ap = (const ulonglong2*)&As[k2][ty << 3];
            ulonglong2 q;
            q = ap[0]; a[0] = q.x; a[1] = q.y;
            q = ap[1]; a[2] = q.x; a[3] = q.y;
            q = ap[2]; a[4] = q.x; a[5] = q.y;
            q = ap[3]; a[6] = q.x; a[7] = q.y;
#pragma unroll
            for (int m = 0; m < 8; m++) b[m] = Bs[k2][tx + (m << 4)];
#pragma unroll
            for (int i = 0; i < 8; i++)
#pragma unroll
                for (int j = 0; j < 8; j++) ffma2(acc[i][j], a[i], b[j]);
        }
        __syncthreads();
    }

#pragma unroll
    for (int i = 0; i < 8; i++) {
        int t = t0 + (ty << 3) + i;
#pragma unroll
        for (int m = 0; m < 8; m++) {
            int g = g0 + tx + (m << 4);
            if (g < G3) {
                float x, y; ull2f2(acc[i][m], x, y);
                out[(size_t)t * G3 + g] = x + y + sBias[tx + (m << 4)];
            }
        }
    }
}

// =====================================================================
// K2a: GRU recurrence via 16-CTA cluster + DSMEM push (primary path).
// 16 CTAs x 512 threads; warp owns 2 units (16-lane split); full h in
// local smem (double-buffered); per-step exchange = st.shared::cluster
// push + barrier.cluster (no L2 on the critical path).
// =====================================================================
__global__ __launch_bounds__(512, 1) void gru_rec_cluster(
    const float* __restrict__ Whh, const float* __restrict__ bhh,
    const float* __restrict__ h0_in, float* __restrict__ dOut, int mode)
{
    const float* gi = mode ? gGiDec : gGiEnc;
    const int tid  = threadIdx.x;
    const int warp = tid >> 5;        // 0..15
    const int lane = tid & 31;
    const int hl   = lane & 15;       // lane within 16-group
    const int uoff = lane >> 4;       // 0 or 1
    const unsigned rank = cluster_rank();
    const int j = (int)rank * 32 + warp * 2 + uoff;   // unit id, <512
    const bool jv = (j < HID);

    __shared__ __align__(16) float sH[2][512];
    __shared__ __align__(16) float sSlice[32];

    // packed weights: 8 float4 chunks per gate, k = hl*4 + i*64
    unsigned long long wr2[16], wz2[16], wn2[16];
#pragma unroll
    for (int i = 0; i < 8; i++) {
        int kb = (hl << 2) + (i << 6);
        float4 a = make_float4(0.f,0.f,0.f,0.f), b = a, c = a;
        if (jv && kb < HID) {          // HID%4==0: chunks fully in or out
            a = *(const float4*)(Whh + (size_t)j * HID + kb);
            b = *(const float4*)(Whh + (size_t)(j + HID) * HID + kb);
            c = *(const float4*)(Whh + (size_t)(j + 2 * HID) * HID + kb);
        }
        wr2[i*2+0] = f22ull(a.x, a.y); wr2[i*2+1] = f22ull(a.z, a.w);
        wz2[i*2+0] = f22ull(b.x, b.y); wz2[i*2+1] = f22ull(b.z, b.w);
        wn2[i*2+0] = f22ull(c.x, c.y); wn2[i*2+1] = f22ull(c.z, c.w);
    }
    float br = 0.f, bz = 0.f, bn = 0.f;
    if (jv) { br = bhh[j]; bz = bhh[j + HID]; bn = bhh[j + 2 * HID]; }

    // init both buffers (pad 500..511 = 0, maintained by forced-zero pushes)
    {
        const float* src = mode ? gHfinal : h0_in;
        sH[0][tid] = (tid < HID) ? src[tid] : 0.f;
        sH[1][tid] = 0.f;
    }

    // prefetch gi for step 0
    float gir = 0.f, giz = 0.f, gin = 0.f;
    if (hl == 0 && jv) {
        const float* g0 = gi + j;
        gir = g0[0]; giz = g0[HID]; gin = g0[2 * HID];
    }

    // precompute DSMEM push targets: this CTA's slice slot in peer `warp`
    const unsigned dstA = mapa_cta(smem_u32(&sH[1][rank * 32 + lane]), (unsigned)warp);
    const unsigned dstB = mapa_cta(smem_u32(&sH[0][rank * 32 + lane]), (unsigned)warp);
    __syncthreads();

    for (int s = 0; s < S_LEN; s++) {
        const float* cur = sH[s & 1];

        unsigned long long aR = 0ull, aZ = 0ull, aN = 0ull;
#pragma unroll
        for (int i = 0; i < 8; i++) {
            float4 hv = *(const float4*)(cur + (hl << 2) + (i << 6));
            unsigned long long hx = f22ull(hv.x, hv.y);
            unsigned long long hy = f22ull(hv.z, hv.w);
            ffma2(aR, wr2[i*2+0], hx); ffma2(aR, wr2[i*2+1], hy);
            ffma2(aZ, wz2[i*2+0], hx); ffma2(aZ, wz2[i*2+1], hy);
            ffma2(aN, wn2[i*2+0], hx); ffma2(aN, wn2[i*2+1], hy);
        }
        float x, y;
        ull2f2(aR, x, y); float ar = x + y;
        ull2f2(aZ, x, y); float az = x + y;
        ull2f2(aN, x, y); float an = x + y;
#pragma unroll
        for (int off = 8; off; off >>= 1) {      // reduce within 16-lane group
            ar += __shfl_xor_sync(0xffffffffu, ar, off);
            az += __shfl_xor_sync(0xffffffffu, az, off);
            an += __shfl_xor_sync(0xffffffffu, an, off);
        }
        if (hl == 0) {
            float val = 0.f;
            if (jv) {
                float hold = cur[j];
                float r = sigmoid_fast(gir + ar + br);
                float z = sigmoid_fast(giz + az + bz);
                float n = tanh_fast(gin + r * (an + bn));
                val = (1.f - z) * n + z * hold;
            }
            sSlice[warp * 2 + uoff] = val;
        }
        __syncthreads();                          // slice staged; cur reads done

        // push slice (32 floats) to peer CTA `warp`'s next buffer
        {
            float v = sSlice[lane];
            unsigned dst = (s & 1) ? dstB : dstA;
            asm volatile("st.shared::cluster.f32 [%0], %1;" :: "r"(dst), "f"(v) : "memory");
            if (mode && warp == 0 && ((int)rank * 32 + lane) < HID)
                __stcg(gDecHs + (size_t)s * HID + rank * 32 + lane, v);
        }
        CLUSTER_ARRIVE();
        if (hl == 0 && jv && s + 1 < S_LEN) {     // gi prefetch hides in barrier
            const float* gs = gi + (size_t)(s + 1) * G3 + j;
            gir = gs[0]; giz = gs[HID]; gin = gs[2 * HID];
        }
        CLUSTER_WAIT();                           // remote pushes now visible
    }

    if (!mode && rank == 0) {                     // final h is in sH[0]
        gHfinal[tid] = sH[0][tid];
        if (tid < HID) dOut[1 + tid] = sH[0][tid];
    }
}

// =====================================================================
// K2b: fallback GRU recurrence (R13 mailbox version) if cluster-16
// is unsupported. 25 blocks x 640 threads.
// =====================================================================
__global__ __launch_bounds__(640, 1) void gru_rec_kernel(
    const float* __restrict__ Whh, const float* __restrict__ bhh,
    const float* __restrict__ h0_in, float* __restrict__ dOut,
    int mode, unsigned flagBase)
{
    const float* gi = mode ? gGiDec : gGiEnc;
    const int tid  = threadIdx.x;
    const int warp = tid >> 5;
    const int lane = tid & 31;
    const int j = blockIdx.x * RWPB + warp;

    __shared__ __align__(16) float sH[512];
    __shared__ __align__(16) float sStage[RWPB];

    unsigned long long wr2[8], wz2[8], wn2[8];
#pragma unroll
    for (int i = 0; i < 4; i++) {
        int kb = (i << 7) + (lane << 2);
        float4 a = make_float4(0.f,0.f,0.f,0.f), b = a, c = a;
        if (kb + 3 < HID) {
            a = *(const float4*)(Whh + (size_t)j * HID + kb);
            b = *(const float4*)(Whh + (size_t)(j + HID) * HID + kb);
            c = *(const float4*)(Whh + (size_t)(j + 2 * HID) * HID + kb);
        }
        wr2[i*2+0] = f22ull(a.x, a.y); wr2[i*2+1] = f22ull(a.z, a.w);
        wz2[i*2+0] = f22ull(b.x, b.y); wz2[i*2+1] = f22ull(b.z, b.w);
        wn2[i*2+0] = f22ull(c.x, c.y); wn2[i*2+1] = f22ull(c.z, c.w);
    }
    const float br = bhh[j], bz = bhh[j + HID], bn = bhh[j + 2 * HID];

    if (tid < 128) {
        float4 v = make_float4(0.f, 0.f, 0.f, 0.f);
        if (tid < 125) {
            if (mode) v = *(const float4*)(gHfinal + tid * 4);
            else      v = *(const float4*)(h0_in + tid * 4);
        }
        *(float4*)(sH + tid * 4) = v;
    }

    float gir = 0.f, giz = 0.f, gin = 0.f;
    if (lane == 0) {
        const float* g0 = gi + j;
        gir = g0[0]; giz = g0[HID]; gin = g0[2 * HID];
    }
    __syncthreads();

    for (int s = 0; s < S_LEN; s++) {
        unsigned long long h2[8];
#pragma unroll
        for (int i = 0; i < 4; i++) {
            ulonglong2 q = *(const ulonglong2*)(sH + (i << 7) + (lane << 2));
            h2[i*2] = q.x; h2[i*2+1] = q.y;
        }
        float hold = 0.f;
        if (lane == 0) hold = sH[j];

        unsigned long long aR = 0ull, aZ = 0ull, aN = 0ull;
#pragma unroll
        for (int i = 0; i < 8; i++) {
            ffma2(aR, wr2[i], h2[i]);
            ffma2(aZ, wz2[i], h2[i]);
            ffma2(aN, wn2[i], h2[i]);
        }
        float x, y;
        ull2f2(aR, x, y); float ar = x + y;
        ull2f2(aZ, x, y); float az = x + y;
        ull2f2(aN, x, y); float an = x + y;
#pragma unroll
        for (int off = 16; off; off >>= 1) {
            ar += __shfl_xor_sync(0xffffffffu, ar, off);
            az += __shfl_xor_sync(0xffffffffu, az, off);
            an += __shfl_xor_sync(0xffffffffu, an, off);
        }
        if (lane == 0) {
            float r = sigmoid_fast(gir + ar + br);
            float z = sigmoid_fast(giz + az + bz);
            float n = tanh_fast(gin + r * (an + bn));
            sStage[warp] = (1.f - z) * n + z * hold;
            if (s + 1 < S_LEN) {
                const float* gs = gi + (size_t)(s + 1) * G3 + j;
                gir = gs[0]; giz = gs[HID]; gin = gs[2 * HID];
            }
        }
        __syncthreads();

        const unsigned want = flagBase + 1u + (unsigned)s;
        if (warp == 0) {
            if (lane == 0) {
                float* line = gHx[s & 1][blockIdx.x];
                float4 d0 = *(const float4*)(sStage + 0);
                float4 d1 = *(const float4*)(sStage + 4);
                float4 d2 = *(const float4*)(sStage + 8);
                float4 d3 = *(const float4*)(sStage + 12);
                float4 d4 = *(const float4*)(sStage + 16);
                __stcg((float4*)line + 0, d0);
                __stcg((float4*)line + 1, d1);
                __stcg((float4*)line + 2, d2);
                __stcg((float4*)line + 3, d3);
                __stcg((float4*)line + 4, d4);
                st_rel((unsigned*)(line + 31), want);
                if (mode) {
                    float4* hp = (float4*)(gDecHs + (size_t)s * HID + blockIdx.x * RWPB);
                    __stcg(hp + 0, d0); __stcg(hp + 1, d1); __stcg(hp + 2, d2);
                    __stcg(hp + 3, d3); __stcg(hp + 4, d4);
                }
            }
            if (lane < RBLK) {
                const float* line = gHx[s & 1][lane];
                const unsigned* fp = (const unsigned*)(line + 31);
                while (ld_acq(fp) < want) { }
                float4 v0 = __ldcg((const float4*)line + 0);
                float4 v1 = __ldcg((const float4*)line + 1);
                float4 v2 = __ldcg((const float4*)line + 2);
                float4 v3 = __ldcg((const float4*)line + 3);
                float4 v4 = __ldcg((const float4*)line + 4);
                float* dst = sH + lane * RWPB;
                *(float4*)(dst + 0)  = v0;
                *(float4*)(dst + 4)  = v1;
                *(float4*)(dst + 8)  = v2;
                *(float4*)(dst + 12) = v3;
                *(float4*)(dst + 16) = v4;
            }
        }
        __syncthreads();
    }

    if (!mode && blockIdx.x == 0) {
        if (tid < 512) gHfinal[tid] = sH[tid];
        if (tid < HID) dOut[1 + tid] = sH[tid];
    }
}

// =====================================================================
// K3: logits = dec_hs @ outW^T + outB (R13 version, 512 threads).
// =====================================================================
__global__ __launch_bounds__(512, 1) void logits_kernel(
    const float* __restrict__ outW, const float* __restrict__ outB,
    const int* __restrict__ target)
{
    const int t0 = blockIdx.y * 128;
    const int v0 = blockIdx.x * 128;

    __shared__ __align__(16) unsigned long long As[2][10][128];
    __shared__ __align__(16) unsigned long long Bs[2][10][128];
    __shared__ float sOb[128];
    __shared__ float sRowMax[128];
    __shared__ int   sRowIdx[128];

    const int tid = threadIdx.x;
    if (tid < 128) {
        int v = v0 + tid;
        sOb[tid] = (v < VOC) ? outB[v] : 0.f;
    }

    unsigned long long acc[4][8];
#pragma unroll
    for (int i = 0; i < 4; i++)
#pragma unroll
        for (int m = 0; m < 8; m++) acc[i][m] = 0ull;

    const int ty = tid >> 4, tx = tid & 15;

    {
#pragma unroll
        for (int r = 0; r < 5; r++) {
            int id = tid + r * 512;
            if (id < 1280) {
                int k2 = id >> 7, col = id & 127;
                float2 av = *(const float2*)(gDecHs + (size_t)(t0 + col) * HID + k2 * 2);
                As[0][k2][col] = f22ull(av.x, av.y);
            } else {
                int e = id - 1280;
                int k2 = e >> 7, col = e & 127;
                int v = v0 + col;
                float2 bv = make_float2(0.f, 0.f);
                if (v < VOC) bv = *(const float2*)(outW + (size_t)v * HID + k2 * 2);
                Bs[0][k2][col] = f22ull(bv.x, bv.y);
            }
        }
    }
    __syncthreads();

    for (int kc = 0; kc < 25; kc++) {
        const int cur = kc & 1, nxt = cur ^ 1;

        unsigned long long st[5];
        if (kc < 24) {
            const int kb = (kc + 1) * 20;
#pragma unroll
            for (int r = 0; r < 5; r++) {
                int id = tid + r * 512;
                if (id < 1280) {
                    int k2 = id >> 7, col = id & 127;
                    float2 av = *(const float2*)(gDecHs + (size_t)(t0 + col) * HID + kb + k2 * 2);
                    st[r] = f22ull(av.x, av.y);
                } else {
                    int e = id - 1280;
                    int k2 = e >> 7, col = e & 127;
                    int v = v0 + col;
                    float2 bv = make_float2(0.f, 0.f);
                    if (v < VOC) bv = *(const float2*)(outW + (size_t)v * HID + kb + k2 * 2);
                    st[r] = f22ull(bv.x, bv.y);
                }
            }
        }

#pragma unroll
        for (int k2 = 0; k2 < 10; k2++) {
            unsigned long long a[4], b[8];
            ulonglong2 q;
            const ulonglong2* ap = (const ulonglong2*)&As[cur][k2][ty << 2];
            q = ap[0]; a[0] = q.x; a[1] = q.y;
            q = ap[1]; a[2] = q.x; a[3] = q.y;
#pragma unroll
            for (int p = 0; p < 4; p++) {
                q = *(const ulonglong2*)&Bs[cur][k2][(tx << 1) + (p << 5)];
                b[p*2] = q.x; b[p*2+1] = q.y;
            }
#pragma unroll
            for (int i = 0; i < 4; i++)
#pragma unroll
                for (int m = 0; m < 8; m++) ffma2(acc[i][m], a[i], b[m]);
        }

        if (kc < 24) {
#pragma unroll
            for (int r = 0; r < 5; r++) {
                int id = tid + r * 512;
                if (id < 1280) {
                    int k2 = id >> 7, col = id & 127;
                    As[nxt][k2][col] = st[r];
                } else {
                    int e = id - 1280;
                    int k2 = e >> 7, col = e & 127;
                    Bs[nxt][k2][col] = st[r];
                }
            }
        }
        __syncthreads();
    }

    float* sM = (float*)As;
    int*   sI = (int*)Bs;

#pragma unroll
    for (int i = 0; i < 4; i++) {
        int row = (ty << 2) + i;
        int t = t0 + row;
        int tgt = target[t];
        float lmax = -1e30f; int lidx = 0;
#pragma unroll
        for (int m = 0; m < 8; m++) {
            int col = (tx << 1) + ((m >> 1) << 5) + (m & 1);
            int v = v0 + col;
            if (v < VOC) {
                float x, y; ull2f2(acc[i][m], x, y);
                float logit = x + y + sOb[col];
                if (logit > lmax) { lmax = logit; lidx = v; }
                if (v == tgt) gTlogit[t] = logit;
            }
        }
        sM[row * 16 + tx] = lmax;
        sI[row * 16 + tx] = lidx;
    }
    __syncthreads();

    if (tid < 128) {
        float m = -1e30f; int idx = 0x7fffffff;
        for (int e = 0; e < 16; e++) {
            float me = sM[tid * 16 + e]; int ie = sI[tid * 16 + e];
            if (me > m || (me == m && ie < idx)) { m = me; idx = ie; }
        }
        sRowMax[tid] = m; sRowIdx[tid] = idx;
    }
    __syncthreads();

    float* sS = (float*)Bs;
#pragma unroll
    for (int i = 0; i < 4; i++) {
        int row = (ty << 2) + i;
        float rmax = sRowMax[row];
        float lsum = 0.f;
#pragma unroll
        for (int m = 0; m < 8; m++) {
            int col = (tx << 1) + ((m >> 1) << 5) + (m & 1);
            int v = v0 + col;
            if (v < VOC) {
                float x, y; ull2f2(acc[i][m], x, y);
                lsum += __expf(x + y + sOb[col] - rmax);
            }
        }
        sS[row * 16 + tx] = lsum;
    }
    __syncthreads();

    if (tid < 128) {
        float s = 0.f;
        for (int e = 0; e < 16; e++) s += sS[tid * 16 + e];
        int t = t0 + tid;
        size_t o = (size_t)t * NVT + blockIdx.x;
        gPmax[o] = sRowMax[tid];
        gPidx[o] = sRowIdx[tid];
        gPsum[o] = s;
    }
}

// =====================================================================
// K4: per-row cross-tile reduction -> argmax + NLL.
// =====================================================================
__global__ __launch_bounds__(128) void finalize_kernel(float* __restrict__ dOut)
{
    const int t = blockIdx.x;
    const int tid = threadIdx.x;
    __shared__ float rm[128];
    __shared__ int   ri[128];
    __shared__ float rs[128];

    float m = -1e30f; int idx = 0x7fffffff;
    for (int vt = tid; vt < NVT; vt += 128) {
        float mv = gPmax[(size_t)t * NVT + vt];
        int   iv = gPidx[(size_t)t * NVT + vt];
        if (mv > m || (mv == m && iv < idx)) { m = mv; idx = iv; }
    }
    rm[tid] = m; ri[tid] = idx;
    __syncthreads();
    for (int off = 64; off; off >>= 1) {
        if (tid < off) {
            float m2 = rm[tid + off]; int i2 = ri[tid + off];
            if (m2 > rm[tid] || (m2 == rm[tid] && i2 < ri[tid])) { rm[tid] = m2; ri[tid] = i2; }
        }
        __syncthreads();
    }
    float gmax = rm[0]; int gidx = ri[0];

    float s = 0.f;
    for (int vt = tid; vt < NVT; vt += 128) {
        size_t o = (size_t)t * NVT + vt;
        s += gPsum[o] * expf(gPmax[o] - gmax);
    }
    rs[tid] = s;
    __syncthreads();
    for (int off = 64; off; off >>= 1) {
        if (tid < off) rs[tid] += rs[tid + off];
        __syncthreads();
    }
    if (tid == 0) {
        float lse = gmax + logf(rs[0]);
        gNll[t] = lse - gTlogit[t];
        dOut[1 + HID + t] = (float)gidx;
    }
}

// =====================================================================
// K5: loss = sum(gNll).
// =====================================================================
__global__ __launch_bounds__(512) void loss_kernel(float* __restrict__ dOut)
{
    __shared__ float rs[512];
    int tid = threadIdx.x;
    rs[tid] = gNll[tid];
    __syncthreads();
    for (int off = 256; off; off >>= 1) {
        if (tid < off) rs[tid] += rs[tid + off];
        __syncthreads();
    }
    if (tid == 0) dOut[0] = rs[0];
}

// =====================================================================
extern "C" void kernel_launch(void* const* d_in, const int* in_sizes, int n_in,
                              void* d_out, int out_size)
{
    const int*   encTok = (const int*)d_in[0];
    const int*   tgtTok = (const int*)d_in[1];
    const float* encH0  = (const float*)d_in[2];
    const float* encEmb = (const float*)d_in[3];
    const float* encWih = (const float*)d_in[4];
    const float* encWhh = (const float*)d_in[5];
    const float* encBih = (const float*)d_in[6];
    const float* encBhh = (const float*)d_in[7];
    const float* decEmb = (const float*)d_in[8];
    const float* decWih = (const float*)d_in[9];
    const float* decWhh = (const float*)d_in[10];
    const float* decBih = (const float*)d_in[11];
    const float* decBhh = (const float*)d_in[12];
    const float* outW   = (const float*)d_in[13];
    const float* outB   = (const float*)d_in[14];
    float* out = (float*)d_out;

    gi_gemm_kernel<<<dim3(12, 4, 2), 256>>>(encTok, tgtTok, encEmb, decEmb,
                                            encWih, decWih, encBih, decBih);

    // probe cluster-16 support (pure query, deterministic, capture-safe)
    cudaFuncSetAttribute(gru_rec_cluster,
                         cudaFuncAttributeNonPortableClusterSizeAllowed, 1);
    cudaLaunchConfig_t cfg = {};
    cfg.gridDim  = dim3(CLN, 1, 1);
    cfg.blockDim = dim3(512, 1, 1);
    cfg.dynamicSmemBytes = 0;
    cfg.stream = 0;
    int maxC = 0;
    cudaOccupancyMaxPotentialClusterSize(&maxC, gru_rec_cluster, &cfg);

    if (maxC >= CLN) {
        cudaLaunchAttribute at[1];
        at[0].id = cudaLaunchAttributeClusterDimension;
        at[0].val.clusterDim.x = CLN;
        at[0].val.clusterDim.y = 1;
        at[0].val.clusterDim.z = 1;
        cfg.attrs = at;
        cfg.numAttrs = 1;
        int m0 = 0, m1 = 1;
        cudaLaunchKernelEx(&cfg, gru_rec_cluster, encWhh, encBhh, encH0, out, m0);
        cudaLaunchKernelEx(&cfg, gru_rec_cluster, decWhh, decBhh, encH0, out, m1);
    } else {
        reset_kernel<<<2, 800>>>();
        gru_rec_kernel<<<RBLK, 640>>>(encWhh, encBhh, encH0, out, 0, 0u);
        gru_rec_kernel<<<RBLK, 640>>>(decWhh, decBhh, encH0, out, 1, 512u);
    }

    logits_kernel<<<dim3(NVT, 4), 512>>>(outW, outB, tgtTok);
    finalize_kernel<<<512, 128>>>(out);
    loss_kernel<<<1, 512>>>(out);
}

// round 15
// speedup vs baseline: 1.8488x; 1.0622x over previous
#include <cuda_runtime.h>
#include <cuda_bf16.h>

#define S_LEN 512
#define HID   500
#define G3    1500
#define VOC   50000
#define NVT   391          // ceil(50000/128)
#define RBLK  25           // fallback recurrence blocks
#define RWPB  20           // fallback warps per block
#define CLN   16           // cluster size for DSMEM recurrence
#define NJOB  (NVT * 4)    // logits tile jobs (391 vtiles x 4 tgroups)
#define MGRID (CLN + 1568) // mega grid: 16 rec CTAs + 1568 workers (mult of 16)

// ---------------- static device scratch ----------------
__device__ float gGiEnc[S_LEN * G3];
__device__ float gGiDec[S_LEN * G3];
// fallback mailbox lines
__device__ __align__(128) float gHx[2][RBLK][32];
__device__ __align__(16) float gHfinal[512];
__device__ float gDecHs[S_LEN * HID];
__device__ float gPmax[S_LEN * NVT];
__device__ float gPsum[S_LEN * NVT];
__device__ int   gPidx[S_LEN * NVT];
__device__ float gTlogit[S_LEN];
__device__ float gNll[S_LEN];
// per-rec-CTA progress flags (line-isolated: 32 unsigned = 128B apart)
__device__ __align__(128) unsigned gStepFlag[CLN * 32];

// ---------------- helpers ----------------
__device__ __forceinline__ unsigned long long f22ull(float x, float y) {
    unsigned long long u;
    asm("mov.b64 %0, {%1, %2};" : "=l"(u) : "f"(x), "f"(y));
    return u;
}
__device__ __forceinline__ void ull2f2(unsigned long long u, float& x, float& y) {
    asm("mov.b64 {%0, %1}, %2;" : "=f"(x), "=f"(y) : "l"(u));
}
__device__ __forceinline__ void ffma2(unsigned long long& d, unsigned long long a, unsigned long long b) {
    asm("fma.rn.f32x2 %0, %1, %2, %0;" : "+l"(d) : "l"(a), "l"(b));
}
__device__ __forceinline__ unsigned ld_acq(const unsigned* p) {
    unsigned v;
    asm volatile("ld.acquire.gpu.global.u32 %0, [%1];" : "=r"(v) : "l"(p) : "memory");
    return v;
}
__device__ __forceinline__ void st_rel(unsigned* p, unsigned v) {
    asm volatile("st.release.gpu.global.u32 [%0], %1;" :: "l"(p), "r"(v) : "memory");
}
__device__ __forceinline__ float sigmoid_fast(float x) {
    return __fdividef(1.f, 1.f + __expf(-x));
}
__device__ __forceinline__ float tanh_fast(float x) {
    return __fdividef(2.f, 1.f + __expf(-2.f * x)) - 1.f;
}
__device__ __forceinline__ unsigned smem_u32(const void* p) {
    return (unsigned)__cvta_generic_to_shared(p);
}
__device__ __forceinline__ unsigned cluster_rank() {
    unsigned r; asm("mov.u32 %0, %%cluster_ctarank;" : "=r"(r)); return r;
}
__device__ __forceinline__ unsigned mapa_cta(unsigned saddr, unsigned rank) {
    unsigned r;
    asm("mapa.shared::cluster.u32 %0, %1, %2;" : "=r"(r) : "r"(saddr), "r"(rank));
    return r;
}
#define CLUSTER_ARRIVE() asm volatile("barrier.cluster.arrive.aligned;" ::: "memory")
#define CLUSTER_WAIT()   asm volatile("barrier.cluster.wait.aligned;" ::: "memory")

// smem overlays for the mega kernel
struct SmemLogits {
    unsigned long long As[2][10][128];
    unsigned long long Bs[2][10][128];
    float sOb[128];
    float sRowMax[128];
    int   sRowIdx[128];
};
struct SmemRec {
    float sH[2][512];
    float sSlice[32];
};

// =====================================================================
// K0: reset progress flags + fallback mailbox (replay safety).
// =====================================================================
__global__ void reset_kernel() {
    int i = blockIdx.x * blockDim.x + threadIdx.x;
    if (i < 2 * RBLK * 32) ((float*)gHx)[i] = 0.f;
    if (i < CLN * 32) gStepFlag[i] = 0u;
}

// =====================================================================
// K1: gi = gather(emb, tok)[relu if dec] @ Wih^T + bih   for enc & dec
// =====================================================================
__global__ __launch_bounds__(256, 1) void gi_gemm_kernel(
    const int* __restrict__ encTok, const int* __restrict__ tgtTok,
    const float* __restrict__ encEmb, const float* __restrict__ decEmb,
    const float* __restrict__ encWih, const float* __restrict__ decWih,
    const float* __restrict__ encBih, const float* __restrict__ decBih)
{
    const int mode = blockIdx.z;
    const float* emb  = mode ? decEmb : encEmb;
    const float* W    = mode ? decWih : encWih;
    const float* bias = mode ? decBih : encBih;
    float* out = mode ? gGiDec : gGiEnc;

    const int t0 = blockIdx.y * 128;
    const int g0 = blockIdx.x * 128;

    __shared__ __align__(16) unsigned long long As[10][128];
    __shared__ __align__(16) unsigned long long Bs[10][128];
    __shared__ int   sTok[128];
    __shared__ float sBias[128];

    const int tid = threadIdx.x;
    if (tid < 128) {
        int t = t0 + tid;
        int tok;
        if (mode) tok = (t == 0) ? 0 : tgtTok[t - 1];
        else      tok = encTok[t];
        sTok[tid] = tok;
        int g = g0 + tid;
        sBias[tid] = (g < G3) ? bias[g] : 0.f;
    }
    __syncthreads();

    unsigned long long acc[8][8];
#pragma unroll
    for (int i = 0; i < 8; i++)
#pragma unroll
        for (int j = 0; j < 8; j++) acc[i][j] = 0ull;

    const int ty = tid >> 4, tx = tid & 15;

    for (int kc = 0; kc < 25; kc++) {
        const int kb = kc * 20;
#pragma unroll
        for (int r = 0; r < 5; r++) {
            int id  = tid + r * 256;
            int k2  = id >> 7;
            int col = id & 127;
            const float* ap = emb + (size_t)sTok[col] * HID + kb + k2 * 2;
            float2 av = *(const float2*)ap;
            if (mode) { av.x = fmaxf(av.x, 0.f); av.y = fmaxf(av.y, 0.f); }
            As[k2][col] = f22ull(av.x, av.y);
            int g = g0 + col;
            float2 bv = make_float2(0.f, 0.f);
            if (g < G3) bv = *(const float2*)(W + (size_t)g * HID + kb + k2 * 2);
            Bs[k2][col] = f22ull(bv.x, bv.y);
        }
        __syncthreads();
#pragma unroll
        for (int k2 = 0; k2 < 10; k2++) {
            unsigned long long a[8], b[8];
            const ulonglong2* ap = (const ulonglong2*)&As[k2][ty << 3];
            ulonglong2 q;
            q = ap[0]; a[0] = q.x; a[1] = q.y;
            q = ap[1]; a[2] = q.x; a[3] = q.y;
            q = ap[2]; a[4] = q.x; a[5] = q.y;
            q = ap[3]; a[6] = q.x; a[7] = q.y;
#pragma unroll
            for (int m = 0; m < 8; m++) b[m] = Bs[k2][tx + (m << 4)];
#pragma unroll
            for (int i = 0; i < 8; i++)
#pragma unroll
                for (int j = 0; j < 8; j++) ffma2(acc[i][j], a[i], b[j]);
        }
        __syncthreads();
    }

#pragma unroll
    for (int i = 0; i < 8; i++) {
        int t = t0 + (ty << 3) + i;
#pragma unroll
        for (int m = 0; m < 8; m++) {
            int g = g0 + tx + (m << 4);
            if (g < G3) {
                float x, y; ull2f2(acc[i][m], x, y);
                out[(size_t)t * G3 + g] = x + y + sBias[tx + (m << 4)];
            }
        }
    }
}

// =====================================================================
// K2a: ENCODER GRU recurrence via 16-CTA cluster + DSMEM push (R14).
// =====================================================================
__global__ __launch_bounds__(512, 1) void gru_rec_cluster(
    const float* __restrict__ Whh, const float* __restrict__ bhh,
    const float* __restrict__ h0_in, float* __restrict__ dOut, int mode)
{
    const float* gi = mode ? gGiDec : gGiEnc;
    const int tid  = threadIdx.x;
    const int warp = tid >> 5;
    const int lane = tid & 31;
    const int hl   = lane & 15;
    const int uoff = lane >> 4;
    const unsigned rank = cluster_rank();
    const int j = (int)rank * 32 + warp * 2 + uoff;
    const bool jv = (j < HID);

    __shared__ __align__(16) float sH[2][512];
    __shared__ __align__(16) float sSlice[32];

    unsigned long long wr2[16], wz2[16], wn2[16];
#pragma unroll
    for (int i = 0; i < 8; i++) {
        int kb = (hl << 2) + (i << 6);
        float4 a = make_float4(0.f,0.f,0.f,0.f), b = a, c = a;
        if (jv && kb < HID) {
            a = *(const float4*)(Whh + (size_t)j * HID + kb);
            b = *(const float4*)(Whh + (size_t)(j + HID) * HID + kb);
            c = *(const float4*)(Whh + (size_t)(j + 2 * HID) * HID + kb);
        }
        wr2[i*2+0] = f22ull(a.x, a.y); wr2[i*2+1] = f22ull(a.z, a.w);
        wz2[i*2+0] = f22ull(b.x, b.y); wz2[i*2+1] = f22ull(b.z, b.w);
        wn2[i*2+0] = f22ull(c.x, c.y); wn2[i*2+1] = f22ull(c.z, c.w);
    }
    float br = 0.f, bz = 0.f, bn = 0.f;
    if (jv) { br = bhh[j]; bz = bhh[j + HID]; bn = bhh[j + 2 * HID]; }

    {
        const float* src = mode ? gHfinal : h0_in;
        sH[0][tid] = (tid < HID) ? src[tid] : 0.f;
        sH[1][tid] = 0.f;
    }

    float gir = 0.f, giz = 0.f, gin = 0.f;
    if (hl == 0 && jv) {
        const float* g0 = gi + j;
        gir = g0[0]; giz = g0[HID]; gin = g0[2 * HID];
    }

    const unsigned dstA = mapa_cta(smem_u32(&sH[1][rank * 32 + lane]), (unsigned)warp);
    const unsigned dstB = mapa_cta(smem_u32(&sH[0][rank * 32 + lane]), (unsigned)warp);
    __syncthreads();

    for (int s = 0; s < S_LEN; s++) {
        const float* cur = sH[s & 1];

        unsigned long long aR = 0ull, aZ = 0ull, aN = 0ull;
#pragma unroll
        for (int i = 0; i < 8; i++) {
            float4 hv = *(const float4*)(cur + (hl << 2) + (i << 6));
            unsigned long long hx = f22ull(hv.x, hv.y);
            unsigned long long hy = f22ull(hv.z, hv.w);
            ffma2(aR, wr2[i*2+0], hx); ffma2(aR, wr2[i*2+1], hy);
            ffma2(aZ, wz2[i*2+0], hx); ffma2(aZ, wz2[i*2+1], hy);
            ffma2(aN, wn2[i*2+0], hx); ffma2(aN, wn2[i*2+1], hy);
        }
        float x, y;
        ull2f2(aR, x, y); float ar = x + y;
        ull2f2(aZ, x, y); float az = x + y;
        ull2f2(aN, x, y); float an = x + y;
#pragma unroll
        for (int off = 8; off; off >>= 1) {
            ar += __shfl_xor_sync(0xffffffffu, ar, off);
            az += __shfl_xor_sync(0xffffffffu, az, off);
            an += __shfl_xor_sync(0xffffffffu, an, off);
        }
        if (hl == 0) {
            float val = 0.f;
            if (jv) {
                float hold = cur[j];
                float r = sigmoid_fast(gir + ar + br);
                float z = sigmoid_fast(giz + az + bz);
                float n = tanh_fast(gin + r * (an + bn));
                val = (1.f - z) * n + z * hold;
            }
            sSlice[warp * 2 + uoff] = val;
        }
        __syncthreads();

        {
            float v = sSlice[lane];
            unsigned dst = (s & 1) ? dstB : dstA;
            asm volatile("st.shared::cluster.f32 [%0], %1;" :: "r"(dst), "f"(v) : "memory");
            if (mode && warp == 0 && ((int)rank * 32 + lane) < HID)
                __stcg(gDecHs + (size_t)s * HID + rank * 32 + lane, v);
        }
        CLUSTER_ARRIVE();
        if (hl == 0 && jv && s + 1 < S_LEN) {
            const float* gs = gi + (size_t)(s + 1) * G3 + j;
            gir = gs[0]; giz = gs[HID]; gin = gs[2 * HID];
        }
        CLUSTER_WAIT();
    }

    if (!mode && rank == 0) {
        gHfinal[tid] = sH[0][tid];
        if (tid < HID) dOut[1 + tid] = sH[0][tid];
    }
}

// =====================================================================
// K2c: MEGA kernel — cluster 0 runs the DECODER recurrence and publishes
// per-step progress flags; CTAs 16.. run logits tiles gated on the flags.
// grid = MGRID CTAs x 512 threads, cluster dim 16.
// =====================================================================
__global__ __launch_bounds__(512, 1) void mega_kernel(
    const float* __restrict__ Whh, const float* __restrict__ bhh,
    const float* __restrict__ outW, const float* __restrict__ outB,
    const int* __restrict__ target)
{
    __shared__ __align__(16) char smemRaw[sizeof(SmemLogits)];
    const int tid = threadIdx.x;

    if (blockIdx.x < CLN) {
        // ------------- decoder GRU recurrence (cluster 0) -------------
        SmemRec& S = *reinterpret_cast<SmemRec*>(smemRaw);
        const float* gi = gGiDec;
        const int warp = tid >> 5;
        const int lane = tid & 31;
        const int hl   = lane & 15;
        const int uoff = lane >> 4;
        const unsigned rank = cluster_rank();
        const int j = (int)rank * 32 + warp * 2 + uoff;
        const bool jv = (j < HID);

        unsigned long long wr2[16], wz2[16], wn2[16];
#pragma unroll
        for (int i = 0; i < 8; i++) {
            int kb = (hl << 2) + (i << 6);
            float4 a = make_float4(0.f,0.f,0.f,0.f), b = a, c = a;
            if (jv && kb < HID) {
                a = *(const float4*)(Whh + (size_t)j * HID + kb);
                b = *(const float4*)(Whh + (size_t)(j + HID) * HID + kb);
                c = *(const float4*)(Whh + (size_t)(j + 2 * HID) * HID + kb);
            }
            wr2[i*2+0] = f22ull(a.x, a.y); wr2[i*2+1] = f22ull(a.z, a.w);
            wz2[i*2+0] = f22ull(b.x, b.y); wz2[i*2+1] = f22ull(b.z, b.w);
            wn2[i*2+0] = f22ull(c.x, c.y); wn2[i*2+1] = f22ull(c.z, c.w);
        }
        float br = 0.f, bz = 0.f, bn = 0.f;
        if (jv) { br = bhh[j]; bz = bhh[j + HID]; bn = bhh[j + 2 * HID]; }

        S.sH[0][tid] = (tid < HID) ? gHfinal[tid] : 0.f;
        S.sH[1][tid] = 0.f;

        float gir = 0.f, giz = 0.f, gin = 0.f;
        if (hl == 0 && jv) {
            const float* g0 = gi + j;
            gir = g0[0]; giz = g0[HID]; gin = g0[2 * HID];
        }

        const unsigned dstA = mapa_cta(smem_u32(&S.sH[1][rank * 32 + lane]), (unsigned)warp);
        const unsigned dstB = mapa_cta(smem_u32(&S.sH[0][rank * 32 + lane]), (unsigned)warp);
        __syncthreads();

        for (int s = 0; s < S_LEN; s++) {
            const float* cur = S.sH[s & 1];

            unsigned long long aR = 0ull, aZ = 0ull, aN = 0ull;
#pragma unroll
            for (int i = 0; i < 8; i++) {
                float4 hv = *(const float4*)(cur + (hl << 2) + (i << 6));
                unsigned long long hx = f22ull(hv.x, hv.y);
                unsigned long long hy = f22ull(hv.z, hv.w);
                ffma2(aR, wr2[i*2+0], hx); ffma2(aR, wr2[i*2+1], hy);
                ffma2(aZ, wz2[i*2+0], hx); ffma2(aZ, wz2[i*2+1], hy);
                ffma2(aN, wn2[i*2+0], hx); ffma2(aN, wn2[i*2+1], hy);
            }
            float x, y;
            ull2f2(aR, x, y); float ar = x + y;
            ull2f2(aZ, x, y); float az = x + y;
            ull2f2(aN, x, y); float an = x + y;
#pragma unroll
            for (int off = 8; off; off >>= 1) {
                ar += __shfl_xor_sync(0xffffffffu, ar, off);
                az += __shfl_xor_sync(0xffffffffu, az, off);
                an += __shfl_xor_sync(0xffffffffu, an, off);
            }
            if (hl == 0) {
                float val = 0.f;
                if (jv) {
                    float hold = cur[j];
                    float r = sigmoid_fast(gir + ar + br);
                    float z = sigmoid_fast(giz + az + bz);
                    float n = tanh_fast(gin + r * (an + bn));
                    val = (1.f - z) * n + z * hold;
                }
                S.sSlice[warp * 2 + uoff] = val;
            }
            __syncthreads();

            {
                float v = S.sSlice[lane];
                unsigned dst = (s & 1) ? dstB : dstA;
                asm volatile("st.shared::cluster.f32 [%0], %1;" :: "r"(dst), "f"(v) : "memory");
            }
            if (warp == 0) {
                int col = (int)rank * 32 + lane;
                if (col < HID) __stcg(gDecHs + (size_t)s * HID + col, S.sSlice[lane]);
                __syncwarp();
                if (lane == 0) st_rel(&gStepFlag[rank * 32], (unsigned)s + 1u);
            }
            CLUSTER_ARRIVE();
            if (hl == 0 && jv && s + 1 < S_LEN) {
                const float* gs = gi + (size_t)(s + 1) * G3 + j;
                gir = gs[0]; giz = gs[HID]; gin = gs[2 * HID];
            }
            CLUSTER_WAIT();
        }
        return;
    }

    // ------------- logits worker tiles (gated on progress flags) -------------
    const int job = blockIdx.x - CLN;
    if (job >= NJOB) return;
    const int tg    = job / NVT;
    const int vtile = job % NVT;
    const int t0 = tg * 128;
    const int v0 = vtile * 128;

    // gate: wait until all 16 rec CTAs have completed step (tg+1)*128
    {
        const unsigned thr = (unsigned)(tg + 1) * 128u;
        if (tid < 32) {
            for (;;) {
                unsigned v = (tid < CLN) ? ld_acq(&gStepFlag[tid * 32]) : 0xffffffffu;
                if (__all_sync(0xffffffffu, v >= thr)) break;
            }
        }
        __syncthreads();
    }

    SmemLogits& S = *reinterpret_cast<SmemLogits*>(smemRaw);
    if (tid < 128) {
        int v = v0 + tid;
        S.sOb[tid] = (v < VOC) ? outB[v] : 0.f;
    }

    unsigned long long acc[4][8];
#pragma unroll
    for (int i = 0; i < 4; i++)
#pragma unroll
        for (int m = 0; m < 8; m++) acc[i][m] = 0ull;

    const int ty = tid >> 4, tx = tid & 15;

    {
#pragma unroll
        for (int r = 0; r < 5; r++) {
            int id = tid + r * 512;
            if (id < 1280) {
                int k2 = id >> 7, col = id & 127;
                float2 av = *(const float2*)(gDecHs + (size_t)(t0 + col) * HID + k2 * 2);
                S.As[0][k2][col] = f22ull(av.x, av.y);
            } else {
                int e = id - 1280;
                int k2 = e >> 7, col = e & 127;
                int v = v0 + col;
                float2 bv = make_float2(0.f, 0.f);
                if (v < VOC) bv = *(const float2*)(outW + (size_t)v * HID + k2 * 2);
                S.Bs[0][k2][col] = f22ull(bv.x, bv.y);
            }
        }
    }
    __syncthreads();

    for (int kc = 0; kc < 25; kc++) {
        const int cur = kc & 1, nxt = cur ^ 1;

        unsigned long long st[5];
        if (kc < 24) {
            const int kb = (kc + 1) * 20;
#pragma unroll
            for (int r = 0; r < 5; r++) {
                int id = tid + r * 512;
                if (id < 1280) {
                    int k2 = id >> 7, col = id & 127;
                    float2 av = *(const float2*)(gDecHs + (size_t)(t0 + col) * HID + kb + k2 * 2);
                    st[r] = f22ull(av.x, av.y);
                } else {
                    int e = id - 1280;
                    int k2 = e >> 7, col = e & 127;
                    int v = v0 + col;
                    float2 bv = make_float2(0.f, 0.f);
                    if (v < VOC) bv = *(const float2*)(outW + (size_t)v * HID + kb + k2 * 2);
                    st[r] = f22ull(bv.x, bv.y);
                }
            }
        }

#pragma unroll
        for (int k2 = 0; k2 < 10; k2++) {
            unsigned long long a[4], b[8];
            ulonglong2 q;
            const ulonglong2* ap = (const ulonglong2*)&S.As[cur][k2][ty << 2];
            q = ap[0]; a[0] = q.x; a[1] = q.y;
            q = ap[1]; a[2] = q.x; a[3] = q.y;
#pragma unroll
            for (int p = 0; p < 4; p++) {
                q = *(const ulonglong2*)&S.Bs[cur][k2][(tx << 1) + (p << 5)];
                b[p*2] = q.x; b[p*2+1] = q.y;
            }
#pragma unroll
            for (int i = 0; i < 4; i++)
#pragma unroll
                for (int m = 0; m < 8; m++) ffma2(acc[i][m], a[i], b[m]);
        }

        if (kc < 24) {
#pragma unroll
            for (int r = 0; r < 5; r++) {
                int id = tid + r * 512;
                if (id < 1280) {
                    int k2 = id >> 7, col = id & 127;
                    S.As[nxt][k2][col] = st[r];
                } else {
                    int e = id - 1280;
                    int k2 = e >> 7, col = e & 127;
                    S.Bs[nxt][k2][col] = st[r];
                }
            }
        }
        __syncthreads();
    }

    float* sM = (float*)S.As;
    int*   sI = (int*)S.Bs;

#pragma unroll
    for (int i = 0; i < 4; i++) {
        int row = (ty << 2) + i;
        int t = t0 + row;
        int tgt = target[t];
        float lmax = -1e30f; int lidx = 0;
#pragma unroll
        for (int m = 0; m < 8; m++) {
            int col = (tx << 1) + ((m >> 1) << 5) + (m & 1);
            int v = v0 + col;
            if (v < VOC) {
                float x, y; ull2f2(acc[i][m], x, y);
                float logit = x + y + S.sOb[col];
                if (logit > lmax) { lmax = logit; lidx = v; }
                if (v == tgt) gTlogit[t] = logit;
            }
        }
        sM[row * 16 + tx] = lmax;
        sI[row * 16 + tx] = lidx;
    }
    __syncthreads();

    if (tid < 128) {
        float m = -1e30f; int idx = 0x7fffffff;
        for (int e = 0; e < 16; e++) {
            float me = sM[tid * 16 + e]; int ie = sI[tid * 16 + e];
            if (me > m || (me == m && ie < idx)) { m = me; idx = ie; }
        }
        S.sRowMax[tid] = m; S.sRowIdx[tid] = idx;
    }
    __syncthreads();

    float* sS = (float*)S.Bs;
#pragma unroll
    for (int i = 0; i < 4; i++) {
        int row = (ty << 2) + i;
        float rmax = S.sRowMax[row];
        float lsum = 0.f;
#pragma unroll
        for (int m = 0; m < 8; m++) {
            int col = (tx << 1) + ((m >> 1) << 5) + (m & 1);
            int v = v0 + col;
            if (v < VOC) {
                float x, y; ull2f2(acc[i][m], x, y);
                lsum += __expf(x + y + S.sOb[col] - rmax);
            }
        }
        sS[row * 16 + tx] = lsum;
    }
    __syncthreads();

    if (tid < 128) {
        float s = 0.f;
        for (int e = 0; e < 16; e++) s += sS[tid * 16 + e];
        int t = t0 + tid;
        size_t o = (size_t)t * NVT + vtile;
        gPmax[o] = S.sRowMax[tid];
        gPidx[o] = S.sRowIdx[tid];
        gPsum[o] = s;
    }
}

// =====================================================================
// K2b: fallback GRU recurrence (R13 mailbox) if clusters unsupported.
// =====================================================================
__global__ __launch_bounds__(640, 1) void gru_rec_kernel(
    const float* __restrict__ Whh, const float* __restrict__ bhh,
    const float* __restrict__ h0_in, float* __restrict__ dOut,
    int mode, unsigned flagBase)
{
    const float* gi = mode ? gGiDec : gGiEnc;
    const int tid  = threadIdx.x;
    const int warp = tid >> 5;
    const int lane = tid & 31;
    const int j = blockIdx.x * RWPB + warp;

    __shared__ __align__(16) float sH[512];
    __shared__ __align__(16) float sStage[RWPB];

    unsigned long long wr2[8], wz2[8], wn2[8];
#pragma unroll
    for (int i = 0; i < 4; i++) {
        int kb = (i << 7) + (lane << 2);
        float4 a = make_float4(0.f,0.f,0.f,0.f), b = a, c = a;
        if (kb + 3 < HID) {
            a = *(const float4*)(Whh + (size_t)j * HID + kb);
            b = *(const float4*)(Whh + (size_t)(j + HID) * HID + kb);
            c = *(const float4*)(Whh + (size_t)(j + 2 * HID) * HID + kb);
        }
        wr2[i*2+0] = f22ull(a.x, a.y); wr2[i*2+1] = f22ull(a.z, a.w);
        wz2[i*2+0] = f22ull(b.x, b.y); wz2[i*2+1] = f22ull(b.z, b.w);
        wn2[i*2+0] = f22ull(c.x, c.y); wn2[i*2+1] = f22ull(c.z, c.w);
    }
    const float br = bhh[j], bz = bhh[j + HID], bn = bhh[j + 2 * HID];

    if (tid < 128) {
        float4 v = make_float4(0.f, 0.f, 0.f, 0.f);
        if (tid < 125) {
            if (mode) v = *(const float4*)(gHfinal + tid * 4);
            else      v = *(const float4*)(h0_in + tid * 4);
        }
        *(float4*)(sH + tid * 4) = v;
    }

    float gir = 0.f, giz = 0.f, gin = 0.f;
    if (lane == 0) {
        const float* g0 = gi + j;
        gir = g0[0]; giz = g0[HID]; gin = g0[2 * HID];
    }
    __syncthreads();

    for (int s = 0; s < S_LEN; s++) {
        unsigned long long h2[8];
#pragma unroll
        for (int i = 0; i < 4; i++) {
            ulonglong2 q = *(const ulonglong2*)(sH + (i << 7) + (lane << 2));
            h2[i*2] = q.x; h2[i*2+1] = q.y;
        }
        float hold = 0.f;
        if (lane == 0) hold = sH[j];

        unsigned long long aR = 0ull, aZ = 0ull, aN = 0ull;
#pragma unroll
        for (int i = 0; i < 8; i++) {
            ffma2(aR, wr2[i], h2[i]);
            ffma2(aZ, wz2[i], h2[i]);
            ffma2(aN, wn2[i], h2[i]);
        }
        float x, y;
        ull2f2(aR, x, y); float ar = x + y;
        ull2f2(aZ, x, y); float az = x + y;
        ull2f2(aN, x, y); float an = x + y;
#pragma unroll
        for (int off = 16; off; off >>= 1) {
            ar += __shfl_xor_sync(0xffffffffu, ar, off);
            az += __shfl_xor_sync(0xffffffffu, az, off);
            an += __shfl_xor_sync(0xffffffffu, an, off);
        }
        if (lane == 0) {
            float r = sigmoid_fast(gir + ar + br);
            float z = sigmoid_fast(giz + az + bz);
            float n = tanh_fast(gin + r * (an + bn));
            sStage[warp] = (1.f - z) * n + z * hold;
            if (s + 1 < S_LEN) {
                const float* gs = gi + (size_t)(s + 1) * G3 + j;
                gir = gs[0]; giz = gs[HID]; gin = gs[2 * HID];
            }
        }
        __syncthreads();

        const unsigned want = flagBase + 1u + (unsigned)s;
        if (warp == 0) {
            if (lane == 0) {
                float* line = gHx[s & 1][blockIdx.x];
                float4 d0 = *(const float4*)(sStage + 0);
                float4 d1 = *(const float4*)(sStage + 4);
                float4 d2 = *(const float4*)(sStage + 8);
                float4 d3 = *(const float4*)(sStage + 12);
                float4 d4 = *(const float4*)(sStage + 16);
                __stcg((float4*)line + 0, d0);
                __stcg((float4*)line + 1, d1);
                __stcg((float4*)line + 2, d2);
                __stcg((float4*)line + 3, d3);
                __stcg((float4*)line + 4, d4);
                st_rel((unsigned*)(line + 31), want);
                if (mode) {
                    float4* hp = (float4*)(gDecHs + (size_t)s * HID + blockIdx.x * RWPB);
                    __stcg(hp + 0, d0); __stcg(hp + 1, d1); __stcg(hp + 2, d2);
                    __stcg(hp + 3, d3); __stcg(hp + 4, d4);
                }
            }
            if (lane < RBLK) {
                const float* line = gHx[s & 1][lane];
                const unsigned* fp = (const unsigned*)(line + 31);
                while (ld_acq(fp) < want) { }
                float4 v0 = __ldcg((const float4*)line + 0);
                float4 v1 = __ldcg((const float4*)line + 1);
                float4 v2 = __ldcg((const float4*)line + 2);
                float4 v3 = __ldcg((const float4*)line + 3);
                float4 v4 = __ldcg((const float4*)line + 4);
                float* dst = sH + lane * RWPB;
                *(float4*)(dst + 0)  = v0;
                *(float4*)(dst + 4)  = v1;
                *(float4*)(dst + 8)  = v2;
                *(float4*)(dst + 12) = v3;
                *(float4*)(dst + 16) = v4;
            }
        }
        __syncthreads();
    }

    if (!mode && blockIdx.x == 0) {
        if (tid < 512) gHfinal[tid] = sH[tid];
        if (tid < HID) dOut[1 + tid] = sH[tid];
    }
}

// =====================================================================
// K3: standalone logits kernel (fallback path only).
// =====================================================================
__global__ __launch_bounds__(512, 1) void logits_kernel(
    const float* __restrict__ outW, const float* __restrict__ outB,
    const int* __restrict__ target)
{
    const int t0 = blockIdx.y * 128;
    const int v0 = blockIdx.x * 128;

    __shared__ __align__(16) unsigned long long As[2][10][128];
    __shared__ __align__(16) unsigned long long Bs[2][10][128];
    __shared__ float sOb[128];
    __shared__ float sRowMax[128];
    __shared__ int   sRowIdx[128];

    const int tid = threadIdx.x;
    if (tid < 128) {
        int v = v0 + tid;
        sOb[tid] = (v < VOC) ? outB[v] : 0.f;
    }

    unsigned long long acc[4][8];
#pragma unroll
    for (int i = 0; i < 4; i++)
#pragma unroll
        for (int m = 0; m < 8; m++) acc[i][m] = 0ull;

    const int ty = tid >> 4, tx = tid & 15;

    {
#pragma unroll
        for (int r = 0; r < 5; r++) {
            int id = tid + r * 512;
            if (id < 1280) {
                int k2 = id >> 7, col = id & 127;
                float2 av = *(const float2*)(gDecHs + (size_t)(t0 + col) * HID + k2 * 2);
                As[0][k2][col] = f22ull(av.x, av.y);
            } else {
                int e = id - 1280;
                int k2 = e >> 7, col = e & 127;
                int v = v0 + col;
                float2 bv = make_float2(0.f, 0.f);
                if (v < VOC) bv = *(const float2*)(outW + (size_t)v * HID + k2 * 2);
                Bs[0][k2][col] = f22ull(bv.x, bv.y);
            }
        }
    }
    __syncthreads();

    for (int kc = 0; kc < 25; kc++) {
        const int cur = kc & 1, nxt = cur ^ 1;

        unsigned long long st[5];
        if (kc < 24) {
            const int kb = (kc + 1) * 20;
#pragma unroll
            for (int r = 0; r < 5; r++) {
                int id = tid + r * 512;
                if (id < 1280) {
                    int k2 = id >> 7, col = id & 127;
                    float2 av = *(const float2*)(gDecHs + (size_t)(t0 + col) * HID + kb + k2 * 2);
                    st[r] = f22ull(av.x, av.y);
                } else {
                    int e = id - 1280;
                    int k2 = e >> 7, col = e & 127;
                    int v = v0 + col;
                    float2 bv = make_float2(0.f, 0.f);
                    if (v < VOC) bv = *(const float2*)(outW + (size_t)v * HID + kb + k2 * 2);
                    st[r] = f22ull(bv.x, bv.y);
                }
            }
        }

#pragma unroll
        for (int k2 = 0; k2 < 10; k2++) {
            unsigned long long a[4], b[8];
            ulonglong2 q;
            const ulonglong2* ap = (const ulonglong2*)&As[cur][k2][ty << 2];
            q = ap[0]; a[0] = q.x; a[1] = q.y;
            q = ap[1]; a[2] = q.x; a[3] = q.y;
#pragma unroll
            for (int p = 0; p < 4; p++) {
                q = *(const ulonglong2*)&Bs[cur][k2][(tx << 1) + (p << 5)];
                b[p*2] = q.x; b[p*2+1] = q.y;
            }
#pragma unroll
            for (int i = 0; i < 4; i++)
#pragma unroll
                for (int m = 0; m < 8; m++) ffma2(acc[i][m], a[i], b[m]);
        }

        if (kc < 24) {
#pragma unroll
            for (int r = 0; r < 5; r++) {
                int id = tid + r * 512;
                if (id < 1280) {
                    int k2 = id >> 7, col = id & 127;
                    As[nxt][k2][col] = st[r];
                } else {
                    int e = id - 1280;
                    int k2 = e >> 7, col = e & 127;
                    Bs[nxt][k2][col] = st[r];
                }
            }
        }
        __syncthreads();
    }

    float* sM = (float*)As;
    int*   sI = (int*)Bs;

#pragma unroll
    for (int i = 0; i < 4; i++) {
        int row = (ty << 2) + i;
        int t = t0 + row;
        int tgt = target[t];
        float lmax = -1e30f; int lidx = 0;
#pragma unroll
        for (int m = 0; m < 8; m++) {
            int col = (tx << 1) + ((m >> 1) << 5) + (m & 1);
            int v = v0 + col;
            if (v < VOC) {
                float x, y; ull2f2(acc[i][m], x, y);
                float logit = x + y + sOb[col];
                if (logit > lmax) { lmax = logit; lidx = v; }
                if (v == tgt) gTlogit[t] = logit;
            }
        }
        sM[row * 16 + tx] = lmax;
        sI[row * 16 + tx] = lidx;
    }
    __syncthreads();

    if (tid < 128) {
        float m = -1e30f; int idx = 0x7fffffff;
        for (int e = 0; e < 16; e++) {
            float me = sM[tid * 16 + e]; int ie = sI[tid * 16 + e];
            if (me > m || (me == m && ie < idx)) { m = me; idx = ie; }
        }
        sRowMax[tid] = m; sRowIdx[tid] = idx;
    }
    __syncthreads();

    float* sS = (float*)Bs;
#pragma unroll
    for (int i = 0; i < 4; i++) {
        int row = (ty << 2) + i;
        float rmax = sRowMax[row];
        float lsum = 0.f;
#pragma unroll
        for (int m = 0; m < 8; m++) {
            int col = (tx << 1) + ((m >> 1) << 5) + (m & 1);
            int v = v0 + col;
            if (v < VOC) {
                float x, y; ull2f2(acc[i][m], x, y);
                lsum += __expf(x + y + sOb[col] - rmax);
            }
        }
        sS[row * 16 + tx] = lsum;
    }
    __syncthreads();

    if (tid < 128) {
        float s = 0.f;
        for (int e = 0; e < 16; e++) s += sS[tid * 16 + e];
        int t = t0 + tid;
        size_t o = (size_t)t * NVT + blockIdx.x;
        gPmax[o] = sRowMax[tid];
        gPidx[o] = sRowIdx[tid];
        gPsum[o] = s;
    }
}

// =====================================================================
// K4: per-row cross-tile reduction -> argmax + NLL.
// =====================================================================
__global__ __launch_bounds__(128) void finalize_kernel(float* __restrict__ dOut)
{
    const int t = blockIdx.x;
    const int tid = threadIdx.x;
    __shared__ float rm[128];
    __shared__ int   ri[128];
    __shared__ float rs[128];

    float m = -1e30f; int idx = 0x7fffffff;
    for (int vt = tid; vt < NVT; vt += 128) {
        float mv = gPmax[(size_t)t * NVT + vt];
        int   iv = gPidx[(size_t)t * NVT + vt];
        if (mv > m || (mv == m && iv < idx)) { m = mv; idx = iv; }
    }
    rm[tid] = m; ri[tid] = idx;
    __syncthreads();
    for (int off = 64; off; off >>= 1) {
        if (tid < off) {
            float m2 = rm[tid + off]; int i2 = ri[tid + off];
            if (m2 > rm[tid] || (m2 == rm[tid] && i2 < ri[tid])) { rm[tid] = m2; ri[tid] = i2; }
        }
        __syncthreads();
    }
    float gmax = rm[0]; int gidx = ri[0];

    float s = 0.f;
    for (int vt = tid; vt < NVT; vt += 128) {
        size_t o = (size_t)t * NVT + vt;
        s += gPsum[o] * expf(gPmax[o] - gmax);
    }
    rs[tid] = s;
    __syncthreads();
    for (int off = 64; off; off >>= 1) {
        if (tid < off) rs[tid] += rs[tid + off];
        __syncthreads();
    }
    if (tid == 0) {
        float lse = gmax + logf(rs[0]);
        gNll[t] = lse - gTlogit[t];
        dOut[1 + HID + t] = (float)gidx;
    }
}

// =====================================================================
// K5: loss = sum(gNll).
// =====================================================================
__global__ __launch_bounds__(512) void loss_kernel(float* __restrict__ dOut)
{
    __shared__ float rs[512];
    int tid = threadIdx.x;
    rs[tid] = gNll[tid];
    __syncthreads();
    for (int off = 256; off; off >>= 1) {
        if (tid < off) rs[tid] += rs[tid + off];
        __syncthreads();
    }
    if (tid == 0) dOut[0] = rs[0];
}

// =====================================================================
extern "C" void kernel_launch(void* const* d_in, const int* in_sizes, int n_in,
                              void* d_out, int out_size)
{
    const int*   encTok = (const int*)d_in[0];
    const int*   tgtTok = (const int*)d_in[1];
    const float* encH0  = (const float*)d_in[2];
    const float* encEmb = (const float*)d_in[3];
    const float* encWih = (const float*)d_in[4];
    const float* encWhh = (const float*)d_in[5];
    const float* encBih = (const float*)d_in[6];
    const float* encBhh = (const float*)d_in[7];
    const float* decEmb = (const float*)d_in[8];
    const float* decWih = (const float*)d_in[9];
    const float* decWhh = (const float*)d_in[10];
    const float* decBih = (const float*)d_in[11];
    const float* decBhh = (const float*)d_in[12];
    const float* outW   = (const float*)d_in[13];
    const float* outB   = (const float*)d_in[14];
    float* out = (float*)d_out;

    reset_kernel<<<2, 800>>>();
    gi_gemm_kernel<<<dim3(12, 4, 2), 256>>>(encTok, tgtTok, encEmb, decEmb,
                                            encWih, decWih, encBih, decBih);

    cudaFuncSetAttribute(gru_rec_cluster,
                         cudaFuncAttributeNonPortableClusterSizeAllowed, 1);
    cudaFuncSetAttribute(mega_kernel,
                         cudaFuncAttributeNonPortableClusterSizeAllowed, 1);

    cudaLaunchConfig_t cfg = {};
    cfg.gridDim  = dim3(CLN, 1, 1);
    cfg.blockDim = dim3(512, 1, 1);
    cfg.dynamicSmemBytes = 0;
    cfg.stream = 0;
    int maxC = 0;
    cudaOccupancyMaxPotentialClusterSize(&maxC, gru_rec_cluster, &cfg);

    cudaLaunchConfig_t cfg2 = {};
    cfg2.gridDim  = dim3(MGRID, 1, 1);
    cfg2.blockDim = dim3(512, 1, 1);
    cfg2.dynamicSmemBytes = 0;
    cfg2.stream = 0;
    int maxC2 = 0;
    cudaOccupancyMaxPotentialClusterSize(&maxC2, mega_kernel, &cfg2);

    if (maxC >= CLN && maxC2 >= CLN) {
        cudaLaunchAttribute at[1];
        at[0].id = cudaLaunchAttributeClusterDimension;
        at[0].val.clusterDim.x = CLN;
        at[0].val.clusterDim.y = 1;
        at[0].val.clusterDim.z = 1;
        cfg.attrs = at;  cfg.numAttrs = 1;
        cfg2.attrs = at; cfg2.numAttrs = 1;
        int m0 = 0;
        cudaLaunchKernelEx(&cfg, gru_rec_cluster, encWhh, encBhh, encH0, out, m0);
        cudaLaunchKernelEx(&cfg2, mega_kernel, decWhh, decBhh, outW, outB, tgtTok);
    } else {
        gru_rec_kernel<<<RBLK, 640>>>(encWhh, encBhh, encH0, out, 0, 0u);
        gru_rec_kernel<<<RBLK, 640>>>(decWhh, decBhh, encH0, out, 1, 512u);
        logits_kernel<<<dim3(NVT, 4), 512>>>(outW, outB, tgtTok);
    }

    finalize_kernel<<<512, 128>>>(out);
    loss_kernel<<<1, 512>>>(out);
}

// round 16
// speedup vs baseline: 2.2284x; 1.2053x over previous
#include <cuda_runtime.h>
#include <cuda_bf16.h>

#define S_LEN 512
#define HID   500
#define G3    1500
#define VOC   50000
#define NVT   391          // ceil(50000/128)
#define RBLK  25           // fallback recurrence blocks
#define RWPB  20           // fallback warps per block
#define CLN   16           // cluster size for DSMEM recurrence
#define NJOB  (NVT * 4)    // logits tile jobs (391 vtiles x 4 tgroups)
#define MGRID (CLN + 1568) // mega grid: 16 rec CTAs + 1568 workers

// ---------------- static device scratch ----------------
__device__ float gGiEnc[S_LEN * G3];
__device__ float gGiDec[S_LEN * G3];
__device__ __align__(128) float gHx[2][RBLK][32];   // fallback mailboxes
__device__ __align__(16) float gHfinal[512];
__device__ float gDecHs[S_LEN * HID];
__device__ float gPmax[S_LEN * NVT];
__device__ float gPsum[S_LEN * NVT];
__device__ int   gPidx[S_LEN * NVT];
__device__ float gTlogit[S_LEN];
__device__ float gNll[S_LEN];
__device__ __align__(128) unsigned gStepFlag[CLN * 32];

// ---------------- helpers ----------------
__device__ __forceinline__ unsigned long long f22ull(float x, float y) {
    unsigned long long u;
    asm("mov.b64 %0, {%1, %2};" : "=l"(u) : "f"(x), "f"(y));
    return u;
}
__device__ __forceinline__ void ull2f2(unsigned long long u, float& x, float& y) {
    asm("mov.b64 {%0, %1}, %2;" : "=f"(x), "=f"(y) : "l"(u));
}
__device__ __forceinline__ void ffma2(unsigned long long& d, unsigned long long a, unsigned long long b) {
    asm("fma.rn.f32x2 %0, %1, %2, %0;" : "+l"(d) : "l"(a), "l"(b));
}
__device__ __forceinline__ unsigned ld_acq(const unsigned* p) {
    unsigned v;
    asm volatile("ld.acquire.gpu.global.u32 %0, [%1];" : "=r"(v) : "l"(p) : "memory");
    return v;
}
__device__ __forceinline__ void st_rel(unsigned* p, unsigned v) {
    asm volatile("st.release.gpu.global.u32 [%0], %1;" :: "l"(p), "r"(v) : "memory");
}
__device__ __forceinline__ float sigmoid_fast(float x) {
    return __fdividef(1.f, 1.f + __expf(-x));
}
__device__ __forceinline__ float tanh_fast(float x) {
    return __fdividef(2.f, 1.f + __expf(-2.f * x)) - 1.f;
}
__device__ __forceinline__ unsigned smem_u32(const void* p) {
    return (unsigned)__cvta_generic_to_shared(p);
}
__device__ __forceinline__ unsigned cluster_rank() {
    unsigned r; asm("mov.u32 %0, %%cluster_ctarank;" : "=r"(r)); return r;
}
__device__ __forceinline__ unsigned mapa_cta(unsigned saddr, unsigned rank) {
    unsigned r;
    asm("mapa.shared::cluster.u32 %0, %1, %2;" : "=r"(r) : "r"(saddr), "r"(rank));
    return r;
}
__device__ __forceinline__ void mbar_init(unsigned addr, unsigned cnt) {
    asm volatile("mbarrier.init.shared.b64 [%0], %1;" :: "r"(addr), "r"(cnt) : "memory");
}
__device__ __forceinline__ void mbar_arrive_cluster(unsigned addr) {
    asm volatile("mbarrier.arrive.shared::cluster.b64 _, [%0];" :: "r"(addr) : "memory");
}
__device__ __forceinline__ void mbar_wait_acq(unsigned addr, unsigned parity) {
    unsigned done;
    do {
        asm volatile(
            "{\n\t.reg .pred p;\n\t"
            "mbarrier.try_wait.parity.acquire.cluster.shared::cta.b64 p, [%1], %2;\n\t"
            "selp.b32 %0, 1, 0, p;\n\t}"
            : "=r"(done) : "r"(addr), "r"(parity) : "memory");
    } while (!done);
}
#define CLUSTER_SYNC() do { \
    asm volatile("barrier.cluster.arrive.aligned;" ::: "memory"); \
    asm volatile("barrier.cluster.wait.aligned;" ::: "memory"); \
} while (0)

// smem overlays for the mega kernel
struct SmemLogits {
    unsigned long long As[2][10][128];
    unsigned long long Bs[2][10][128];
    float sOb[128];
    float sRowMax[128];
    int   sRowIdx[128];
};
struct SmemRec {
    float sH[2][512];
    float sSlice[2][32];
    unsigned long long mbar[2];
};

// =====================================================================
// K0: reset progress flags + fallback mailbox (replay safety).
// =====================================================================
__global__ void reset_kernel() {
    int i = blockIdx.x * blockDim.x + threadIdx.x;
    if (i < 2 * RBLK * 32) ((float*)gHx)[i] = 0.f;
    if (i < CLN * 32) gStepFlag[i] = 0u;
}

// =====================================================================
// K1: gi = gather(emb, tok)[relu if dec] @ Wih^T + bih   for enc & dec
// =====================================================================
__global__ __launch_bounds__(256, 1) void gi_gemm_kernel(
    const int* __restrict__ encTok, const int* __restrict__ tgtTok,
    const float* __restrict__ encEmb, const float* __restrict__ decEmb,
    const float* __restrict__ encWih, const float* __restrict__ decWih,
    const float* __restrict__ encBih, const float* __restrict__ decBih)
{
    const int mode = blockIdx.z;
    const float* emb  = mode ? decEmb : encEmb;
    const float* W    = mode ? decWih : encWih;
    const float* bias = mode ? decBih : encBih;
    float* out = mode ? gGiDec : gGiEnc;

    const int t0 = blockIdx.y * 128;
    const int g0 = blockIdx.x * 128;

    __shared__ __align__(16) unsigned long long As[10][128];
    __shared__ __align__(16) unsigned long long Bs[10][128];
    __shared__ int   sTok[128];
    __shared__ float sBias[128];

    const int tid = threadIdx.x;
    if (tid < 128) {
        int t = t0 + tid;
        int tok;
        if (mode) tok = (t == 0) ? 0 : tgtTok[t - 1];
        else      tok = encTok[t];
        sTok[tid] = tok;
        int g = g0 + tid;
        sBias[tid] = (g < G3) ? bias[g] : 0.f;
    }
    __syncthreads();

    unsigned long long acc[8][8];
#pragma unroll
    for (int i = 0; i < 8; i++)
#pragma unroll
        for (int j = 0; j < 8; j++) acc[i][j] = 0ull;

    const int ty = tid >> 4, tx = tid & 15;

    for (int kc = 0; kc < 25; kc++) {
        const int kb = kc * 20;
#pragma unroll
        for (int r = 0; r < 5; r++) {
            int id  = tid + r * 256;
            int k2  = id >> 7;
            int col = id & 127;
            const float* ap = emb + (size_t)sTok[col] * HID + kb + k2 * 2;
            float2 av = *(const float2*)ap;
            if (mode) { av.x = fmaxf(av.x, 0.f); av.y = fmaxf(av.y, 0.f); }
            As[k2][col] = f22ull(av.x, av.y);
            int g = g0 + col;
            float2 bv = make_float2(0.f, 0.f);
            if (g < G3) bv = *(const float2*)(W + (size_t)g * HID + kb + k2 * 2);
            Bs[k2][col] = f22ull(bv.x, bv.y);
        }
        __syncthreads();
#pragma unroll
        for (int k2 = 0; k2 < 10; k2++) {
            unsigned long long a[8], b[8];
            const ulonglong2* ap = (const ulonglong2*)&As[k2][ty << 3];
            ulonglong2 q;
            q = ap[0]; a[0] = q.x; a[1] = q.y;
            q = ap[1]; a[2] = q.x; a[3] = q.y;
            q = ap[2]; a[4] = q.x; a[5] = q.y;
            q = ap[3]; a[6] = q.x; a[7] = q.y;
#pragma unroll
            for (int m = 0; m < 8; m++) b[m] = Bs[k2][tx + (m << 4)];
#pragma unroll
            for (int i = 0; i < 8; i++)
#pragma unroll
                for (int j = 0; j < 8; j++) ffma2(acc[i][j], a[i], b[j]);
        }
        __syncthreads();
    }

#pragma unroll
    for (int i = 0; i < 8; i++) {
        int t = t0 + (ty << 3) + i;
#pragma unroll
        for (int m = 0; m < 8; m++) {
            int g = g0 + tx + (m << 4);
            if (g < G3) {
                float x, y; ull2f2(acc[i][m], x, y);
                out[(size_t)t * G3 + g] = x + y + sBias[tx + (m << 4)];
            }
        }
    }
}

// =====================================================================
// K2a: ENCODER GRU recurrence: 16-CTA cluster, DSMEM push + mbarrier
// ping-pong (release-arrive / acquire-trywait) instead of cluster.sync.
// =====================================================================
__global__ __launch_bounds__(512, 1) void gru_rec_cluster(
    const float* __restrict__ Whh, const float* __restrict__ bhh,
    const float* __restrict__ h0_in, float* __restrict__ dOut, int mode)
{
    const float* gi = mode ? gGiDec : gGiEnc;
    const int tid  = threadIdx.x;
    const int warp = tid >> 5;
    const int lane = tid & 31;
    const int hl   = lane & 15;
    const int uoff = lane >> 4;
    const unsigned rank = cluster_rank();
    const int j = (int)rank * 32 + warp * 2 + uoff;
    const bool jv = (j < HID);

    __shared__ __align__(16) float sH[2][512];
    __shared__ __align__(16) float sSlice[2][32];
    __shared__ __align__(8) unsigned long long sMbar[2];

    unsigned long long wr2[16], wz2[16], wn2[16];
#pragma unroll
    for (int i = 0; i < 8; i++) {
        int kb = (hl << 2) + (i << 6);
        float4 a = make_float4(0.f,0.f,0.f,0.f), b = a, c = a;
        if (jv && kb < HID) {
            a = *(const float4*)(Whh + (size_t)j * HID + kb);
            b = *(const float4*)(Whh + (size_t)(j + HID) * HID + kb);
            c = *(const float4*)(Whh + (size_t)(j + 2 * HID) * HID + kb);
        }
        wr2[i*2+0] = f22ull(a.x, a.y); wr2[i*2+1] = f22ull(a.z, a.w);
        wz2[i*2+0] = f22ull(b.x, b.y); wz2[i*2+1] = f22ull(b.z, b.w);
        wn2[i*2+0] = f22ull(c.x, c.y); wn2[i*2+1] = f22ull(c.z, c.w);
    }
    float br = 0.f, bz = 0.f, bn = 0.f;
    if (jv) { br = bhh[j]; bz = bhh[j + HID]; bn = bhh[j + 2 * HID]; }

    {
        const float* src = mode ? gHfinal : h0_in;
        sH[0][tid] = (tid < HID) ? src[tid] : 0.f;
        sH[1][tid] = 0.f;
    }
    if (tid == 0) {
        mbar_init(smem_u32(&sMbar[0]), CLN);
        mbar_init(smem_u32(&sMbar[1]), CLN);
    }

    float gir = 0.f, giz = 0.f, gin = 0.f;
    if (hl == 0 && jv) {
        const float* g0 = gi + j;
        gir = g0[0]; giz = g0[HID]; gin = g0[2 * HID];
    }

    const unsigned dstA = mapa_cta(smem_u32(&sH[1][rank * 32 + lane]), (unsigned)warp);
    const unsigned dstB = mapa_cta(smem_u32(&sH[0][rank * 32 + lane]), (unsigned)warp);
    const unsigned mbR0 = mapa_cta(smem_u32(&sMbar[0]), (unsigned)warp);
    const unsigned mbR1 = mapa_cta(smem_u32(&sMbar[1]), (unsigned)warp);
    __syncthreads();
    CLUSTER_SYNC();                     // mbarriers visible cluster-wide

    for (int s = 0; s < S_LEN; s++) {
        const float* cur = sH[s & 1];

        unsigned long long aR = 0ull, aZ = 0ull, aN = 0ull;
#pragma unroll
        for (int i = 0; i < 8; i++) {
            float4 hv = *(const float4*)(cur + (hl << 2) + (i << 6));
            unsigned long long hx = f22ull(hv.x, hv.y);
            unsigned long long hy = f22ull(hv.z, hv.w);
            ffma2(aR, wr2[i*2+0], hx); ffma2(aR, wr2[i*2+1], hy);
            ffma2(aZ, wz2[i*2+0], hx); ffma2(aZ, wz2[i*2+1], hy);
            ffma2(aN, wn2[i*2+0], hx); ffma2(aN, wn2[i*2+1], hy);
        }
        float x, y;
        ull2f2(aR, x, y); float ar = x + y;
        ull2f2(aZ, x, y); float az = x + y;
        ull2f2(aN, x, y); float an = x + y;
#pragma unroll
        for (int off = 8; off; off >>= 1) {
            ar += __shfl_xor_sync(0xffffffffu, ar, off);
            az += __shfl_xor_sync(0xffffffffu, az, off);
            an += __shfl_xor_sync(0xffffffffu, an, off);
        }
        if (hl == 0) {
            float val = 0.f;
            if (jv) {
                float hold = cur[j];
                float r = sigmoid_fast(gir + ar + br);
                float z = sigmoid_fast(giz + az + bz);
                float n = tanh_fast(gin + r * (an + bn));
                val = (1.f - z) * n + z * hold;
            }
            sSlice[s & 1][warp * 2 + uoff] = val;
            if (jv && s + 1 < S_LEN) {
                const float* gs = gi + (size_t)(s + 1) * G3 + j;
                gir = gs[0]; giz = gs[HID]; gin = gs[2 * HID];
            }
        }
        __syncthreads();                // A: slice staged, cur reads done

        {
            float v = sSlice[s & 1][lane];
            unsigned dst = (s & 1) ? dstB : dstA;
            asm volatile("st.shared::cluster.f32 [%0], %1;" :: "r"(dst), "f"(v) : "memory");
            if (mode && warp == 0 && ((int)rank * 32 + lane) < HID)
                __stcg(gDecHs + (size_t)s * HID + rank * 32 + lane, v);
            __syncwarp();
            if (lane == 0) mbar_arrive_cluster((s & 1) ? mbR1 : mbR0);
        }
        mbar_wait_acq(smem_u32(&sMbar[s & 1]), (unsigned)((s >> 1) & 1));
    }

    if (!mode && rank == 0) {
        gHfinal[tid] = sH[0][tid];
        if (tid < HID) dOut[1 + tid] = sH[0][tid];
    }
}

// =====================================================================
// K2c: MEGA kernel — cluster 0 = decoder recurrence (mbarrier exchange)
// publishing progress flags; CTAs 16.. = gated logits tiles.
// =====================================================================
__global__ __launch_bounds__(512, 1) void mega_kernel(
    const float* __restrict__ Whh, const float* __restrict__ bhh,
    const float* __restrict__ outW, const float* __restrict__ outB,
    const int* __restrict__ target)
{
    __shared__ __align__(16) char smemRaw[sizeof(SmemLogits)];
    const int tid = threadIdx.x;

    if (blockIdx.x < CLN) {
        // ------------- decoder GRU recurrence (cluster 0) -------------
        SmemRec& S = *reinterpret_cast<SmemRec*>(smemRaw);
        const float* gi = gGiDec;
        const int warp = tid >> 5;
        const int lane = tid & 31;
        const int hl   = lane & 15;
        const int uoff = lane >> 4;
        const unsigned rank = cluster_rank();
        const int j = (int)rank * 32 + warp * 2 + uoff;
        const bool jv = (j < HID);

        unsigned long long wr2[16], wz2[16], wn2[16];
#pragma unroll
        for (int i = 0; i < 8; i++) {
            int kb = (hl << 2) + (i << 6);
            float4 a = make_float4(0.f,0.f,0.f,0.f), b = a, c = a;
            if (jv && kb < HID) {
                a = *(const float4*)(Whh + (size_t)j * HID + kb);
                b = *(const float4*)(Whh + (size_t)(j + HID) * HID + kb);
                c = *(const float4*)(Whh + (size_t)(j + 2 * HID) * HID + kb);
            }
            wr2[i*2+0] = f22ull(a.x, a.y); wr2[i*2+1] = f22ull(a.z, a.w);
            wz2[i*2+0] = f22ull(b.x, b.y); wz2[i*2+1] = f22ull(b.z, b.w);
            wn2[i*2+0] = f22ull(c.x, c.y); wn2[i*2+1] = f22ull(c.z, c.w);
        }
        float br = 0.f, bz = 0.f, bn = 0.f;
        if (jv) { br = bhh[j]; bz = bhh[j + HID]; bn = bhh[j + 2 * HID]; }

        S.sH[0][tid] = (tid < HID) ? gHfinal[tid] : 0.f;
        S.sH[1][tid] = 0.f;
        if (tid == 0) {
            mbar_init(smem_u32(&S.mbar[0]), CLN);
            mbar_init(smem_u32(&S.mbar[1]), CLN);
        }

        float gir = 0.f, giz = 0.f, gin = 0.f;
        if (hl == 0 && jv) {
            const float* g0 = gi + j;
            gir = g0[0]; giz = g0[HID]; gin = g0[2 * HID];
        }

        const unsigned dstA = mapa_cta(smem_u32(&S.sH[1][rank * 32 + lane]), (unsigned)warp);
        const unsigned dstB = mapa_cta(smem_u32(&S.sH[0][rank * 32 + lane]), (unsigned)warp);
        const unsigned mbR0 = mapa_cta(smem_u32(&S.mbar[0]), (unsigned)warp);
        const unsigned mbR1 = mapa_cta(smem_u32(&S.mbar[1]), (unsigned)warp);
        __syncthreads();
        CLUSTER_SYNC();

        for (int s = 0; s < S_LEN; s++) {
            const float* cur = S.sH[s & 1];

            unsigned long long aR = 0ull, aZ = 0ull, aN = 0ull;
#pragma unroll
            for (int i = 0; i < 8; i++) {
                float4 hv = *(const float4*)(cur + (hl << 2) + (i << 6));
                unsigned long long hx = f22ull(hv.x, hv.y);
                unsigned long long hy = f22ull(hv.z, hv.w);
                ffma2(aR, wr2[i*2+0], hx); ffma2(aR, wr2[i*2+1], hy);
                ffma2(aZ, wz2[i*2+0], hx); ffma2(aZ, wz2[i*2+1], hy);
                ffma2(aN, wn2[i*2+0], hx); ffma2(aN, wn2[i*2+1], hy);
            }
            float x, y;
            ull2f2(aR, x, y); float ar = x + y;
            ull2f2(aZ, x, y); float az = x + y;
            ull2f2(aN, x, y); float an = x + y;
#pragma unroll
            for (int off = 8; off; off >>= 1) {
                ar += __shfl_xor_sync(0xffffffffu, ar, off);
                az += __shfl_xor_sync(0xffffffffu, az, off);
                an += __shfl_xor_sync(0xffffffffu, an, off);
            }
            if (hl == 0) {
                float val = 0.f;
                if (jv) {
                    float hold = cur[j];
                    float r = sigmoid_fast(gir + ar + br);
                    float z = sigmoid_fast(giz + az + bz);
                    float n = tanh_fast(gin + r * (an + bn));
                    val = (1.f - z) * n + z * hold;
                }
                S.sSlice[s & 1][warp * 2 + uoff] = val;
                if (jv && s + 1 < S_LEN) {
                    const float* gs = gi + (size_t)(s + 1) * G3 + j;
                    gir = gs[0]; giz = gs[HID]; gin = gs[2 * HID];
                }
            }
            __syncthreads();            // A

            {
                float v = S.sSlice[s & 1][lane];
                unsigned dst = (s & 1) ? dstB : dstA;
                asm volatile("st.shared::cluster.f32 [%0], %1;" :: "r"(dst), "f"(v) : "memory");
                __syncwarp();
                if (lane == 0) mbar_arrive_cluster((s & 1) ? mbR1 : mbR0);
            }
            if (warp == 0) {
                int col = (int)rank * 32 + lane;
                if (col < HID) __stcg(gDecHs + (size_t)s * HID + col, S.sSlice[s & 1][lane]);
                __syncwarp();
                if (lane == 0) st_rel(&gStepFlag[rank * 32], (unsigned)s + 1u);
            }
            mbar_wait_acq(smem_u32(&S.mbar[s & 1]), (unsigned)((s >> 1) & 1));
        }
        return;
    }

    // ------------- logits worker tiles (gated on progress flags) -------------
    const int job = blockIdx.x - CLN;
    if (job >= NJOB) return;
    const int tg    = job / NVT;
    const int vtile = job % NVT;
    const int t0 = tg * 128;
    const int v0 = vtile * 128;

    {
        const unsigned thr = (unsigned)(tg + 1) * 128u;
        if (tid < 32) {
            for (;;) {
                unsigned v = (tid < CLN) ? ld_acq(&gStepFlag[tid * 32]) : 0xffffffffu;
                if (__all_sync(0xffffffffu, v >= thr)) break;
            }
        }
        __syncthreads();
    }

    SmemLogits& S = *reinterpret_cast<SmemLogits*>(smemRaw);
    if (tid < 128) {
        int v = v0 + tid;
        S.sOb[tid] = (v < VOC) ? outB[v] : 0.f;
    }

    unsigned long long acc[4][8];
#pragma unroll
    for (int i = 0; i < 4; i++)
#pragma unroll
        for (int m = 0; m < 8; m++) acc[i][m] = 0ull;

    const int ty = tid >> 4, tx = tid & 15;

    {
#pragma unroll
        for (int r = 0; r < 5; r++) {
            int id = tid + r * 512;
            if (id < 1280) {
                int k2 = id >> 7, col = id & 127;
                float2 av = *(const float2*)(gDecHs + (size_t)(t0 + col) * HID + k2 * 2);
                S.As[0][k2][col] = f22ull(av.x, av.y);
            } else {
                int e = id - 1280;
                int k2 = e >> 7, col = e & 127;
                int v = v0 + col;
                float2 bv = make_float2(0.f, 0.f);
                if (v < VOC) bv = *(const float2*)(outW + (size_t)v * HID + k2 * 2);
                S.Bs[0][k2][col] = f22ull(bv.x, bv.y);
            }
        }
    }
    __syncthreads();

    for (int kc = 0; kc < 25; kc++) {
        const int cur = kc & 1, nxt = cur ^ 1;

        unsigned long long st[5];
        if (kc < 24) {
            const int kb = (kc + 1) * 20;
#pragma unroll
            for (int r = 0; r < 5; r++) {
                int id = tid + r * 512;
                if (id < 1280) {
                    int k2 = id >> 7, col = id & 127;
                    float2 av = *(const float2*)(gDecHs + (size_t)(t0 + col) * HID + kb + k2 * 2);
                    st[r] = f22ull(av.x, av.y);
                } else {
                    int e = id - 1280;
                    int k2 = e >> 7, col = e & 127;
                    int v = v0 + col;
                    float2 bv = make_float2(0.f, 0.f);
                    if (v < VOC) bv = *(const float2*)(outW + (size_t)v * HID + kb + k2 * 2);
                    st[r] = f22ull(bv.x, bv.y);
                }
            }
        }

#pragma unroll
        for (int k2 = 0; k2 < 10; k2++) {
            unsigned long long a[4], b[8];
            ulonglong2 q;
            const ulonglong2* ap = (const ulonglong2*)&S.As[cur][k2][ty << 2];
            q = ap[0]; a[0] = q.x; a[1] = q.y;
            q = ap[1]; a[2] = q.x; a[3] = q.y;
#pragma unroll
            for (int p = 0; p < 4; p++) {
                q = *(const ulonglong2*)&S.Bs[cur][k2][(tx << 1) + (p << 5)];
                b[p*2] = q.x; b[p*2+1] = q.y;
            }
#pragma unroll
            for (int i = 0; i < 4; i++)
#pragma unroll
                for (int m = 0; m < 8; m++) ffma2(acc[i][m], a[i], b[m]);
        }

        if (kc < 24) {
#pragma unroll
            for (int r = 0; r < 5; r++) {
                int id = tid + r * 512;
                if (id < 1280) {
                    int k2 = id >> 7, col = id & 127;
                    S.As[nxt][k2][col] = st[r];
                } else {
                    int e = id - 1280;
                    int k2 = e >> 7, col = e & 127;
                    S.Bs[nxt][k2][col] = st[r];
                }
            }
        }
        __syncthreads();
    }

    float* sM = (float*)S.As;
    int*   sI = (int*)S.Bs;

#pragma unroll
    for (int i = 0; i < 4; i++) {
        int row = (ty << 2) + i;
        int t = t0 + row;
        int tgt = target[t];
        float lmax = -1e30f; int lidx = 0;
#pragma unroll
        for (int m = 0; m < 8; m++) {
            int col = (tx << 1) + ((m >> 1) << 5) + (m & 1);
            int v = v0 + col;
            if (v < VOC) {
                float x, y; ull2f2(acc[i][m], x, y);
                float logit = x + y + S.sOb[col];
                if (logit > lmax) { lmax = logit; lidx = v; }
                if (v == tgt) gTlogit[t] = logit;
            }
        }
        sM[row * 16 + tx] = lmax;
        sI[row * 16 + tx] = lidx;
    }
    __syncthreads();

    if (tid < 128) {
        float m = -1e30f; int idx = 0x7fffffff;
        for (int e = 0; e < 16; e++) {
            float me = sM[tid * 16 + e]; int ie = sI[tid * 16 + e];
            if (me > m || (me == m && ie < idx)) { m = me; idx = ie; }
        }
        S.sRowMax[tid] = m; S.sRowIdx[tid] = idx;
    }
    __syncthreads();

    float* sS = (float*)S.Bs;
#pragma unroll
    for (int i = 0; i < 4; i++) {
        int row = (ty << 2) + i;
        float rmax = S.sRowMax[row];
        float lsum = 0.f;
#pragma unroll
        for (int m = 0; m < 8; m++) {
            int col = (tx << 1) + ((m >> 1) << 5) + (m & 1);
            int v = v0 + col;
            if (v < VOC) {
                float x, y; ull2f2(acc[i][m], x, y);
                lsum += __expf(x + y + S.sOb[col] - rmax);
            }
        }
        sS[row * 16 + tx] = lsum;
    }
    __syncthreads();

    if (tid < 128) {
        float s = 0.f;
        for (int e = 0; e < 16; e++) s += sS[tid * 16 + e];
        int t = t0 + tid;
        size_t o = (size_t)t * NVT + vtile;
        gPmax[o] = S.sRowMax[tid];
        gPidx[o] = S.sRowIdx[tid];
        gPsum[o] = s;
    }
}

// =====================================================================
// K2b: fallback GRU recurrence (mailbox) if clusters unsupported.
// =====================================================================
__global__ __launch_bounds__(640, 1) void gru_rec_kernel(
    const float* __restrict__ Whh, const float* __restrict__ bhh,
    const float* __restrict__ h0_in, float* __restrict__ dOut,
    int mode, unsigned flagBase)
{
    const float* gi = mode ? gGiDec : gGiEnc;
    const int tid  = threadIdx.x;
    const int warp = tid >> 5;
    const int lane = tid & 31;
    const int j = blockIdx.x * RWPB + warp;

    __shared__ __align__(16) float sH[512];
    __shared__ __align__(16) float sStage[RWPB];

    unsigned long long wr2[8], wz2[8], wn2[8];
#pragma unroll
    for (int i = 0; i < 4; i++) {
        int kb = (i << 7) + (lane << 2);
        float4 a = make_float4(0.f,0.f,0.f,0.f), b = a, c = a;
        if (kb + 3 < HID) {
            a = *(const float4*)(Whh + (size_t)j * HID + kb);
            b = *(const float4*)(Whh + (size_t)(j + HID) * HID + kb);
            c = *(const float4*)(Whh + (size_t)(j + 2 * HID) * HID + kb);
        }
        wr2[i*2+0] = f22ull(a.x, a.y); wr2[i*2+1] = f22ull(a.z, a.w);
        wz2[i*2+0] = f22ull(b.x, b.y); wz2[i*2+1] = f22ull(b.z, b.w);
        wn2[i*2+0] = f22ull(c.x, c.y); wn2[i*2+1] = f22ull(c.z, c.w);
    }
    const float br = bhh[j], bz = bhh[j + HID], bn = bhh[j + 2 * HID];

    if (tid < 128) {
        float4 v = make_float4(0.f, 0.f, 0.f, 0.f);
        if (tid < 125) {
            if (mode) v = *(const float4*)(gHfinal + tid * 4);
            else      v = *(const float4*)(h0_in + tid * 4);
        }
        *(float4*)(sH + tid * 4) = v;
    }

    float gir = 0.f, giz = 0.f, gin = 0.f;
    if (lane == 0) {
        const float* g0 = gi + j;
        gir = g0[0]; giz = g0[HID]; gin = g0[2 * HID];
    }
    __syncthreads();

    for (int s = 0; s < S_LEN; s++) {
        unsigned long long h2[8];
#pragma unroll
        for (int i = 0; i < 4; i++) {
            ulonglong2 q = *(const ulonglong2*)(sH + (i << 7) + (lane << 2));
            h2[i*2] = q.x; h2[i*2+1] = q.y;
        }
        float hold = 0.f;
        if (lane == 0) hold = sH[j];

        unsigned long long aR = 0ull, aZ = 0ull, aN = 0ull;
#pragma unroll
        for (int i = 0; i < 8; i++) {
            ffma2(aR, wr2[i], h2[i]);
            ffma2(aZ, wz2[i], h2[i]);
            ffma2(aN, wn2[i], h2[i]);
        }
        float x, y;
        ull2f2(aR, x, y); float ar = x + y;
        ull2f2(aZ, x, y); float az = x + y;
        ull2f2(aN, x, y); float an = x + y;
#pragma unroll
        for (int off = 16; off; off >>= 1) {
            ar += __shfl_xor_sync(0xffffffffu, ar, off);
            az += __shfl_xor_sync(0xffffffffu, az, off);
            an += __shfl_xor_sync(0xffffffffu, an, off);
        }
        if (lane == 0) {
            float r = sigmoid_fast(gir + ar + br);
            float z = sigmoid_fast(giz + az + bz);
            float n = tanh_fast(gin + r * (an + bn));
            sStage[warp] = (1.f - z) * n + z * hold;
            if (s + 1 < S_LEN) {
                const float* gs = gi + (size_t)(s + 1) * G3 + j;
                gir = gs[0]; giz = gs[HID]; gin = gs[2 * HID];
            }
        }
        __syncthreads();

        const unsigned want = flagBase + 1u + (unsigned)s;
        if (warp == 0) {
            if (lane == 0) {
                float* line = gHx[s & 1][blockIdx.x];
                float4 d0 = *(const float4*)(sStage + 0);
                float4 d1 = *(const float4*)(sStage + 4);
                float4 d2 = *(const float4*)(sStage + 8);
                float4 d3 = *(const float4*)(sStage + 12);
                float4 d4 = *(const float4*)(sStage + 16);
                __stcg((float4*)line + 0, d0);
                __stcg((float4*)line + 1, d1);
                __stcg((float4*)line + 2, d2);
                __stcg((float4*)line + 3, d3);
                __stcg((float4*)line + 4, d4);
                st_rel((unsigned*)(line + 31), want);
                if (mode) {
                    float4* hp = (float4*)(gDecHs + (size_t)s * HID + blockIdx.x * RWPB);
                    __stcg(hp + 0, d0); __stcg(hp + 1, d1); __stcg(hp + 2, d2);
                    __stcg(hp + 3, d3); __stcg(hp + 4, d4);
                }
            }
            if (lane < RBLK) {
                const float* line = gHx[s & 1][lane];
                const unsigned* fp = (const unsigned*)(line + 31);
                while (ld_acq(fp) < want) { }
                float4 v0 = __ldcg((const float4*)line + 0);
                float4 v1 = __ldcg((const float4*)line + 1);
                float4 v2 = __ldcg((const float4*)line + 2);
                float4 v3 = __ldcg((const float4*)line + 3);
                float4 v4 = __ldcg((const float4*)line + 4);
                float* dst = sH + lane * RWPB;
                *(float4*)(dst + 0)  = v0;
                *(float4*)(dst + 4)  = v1;
                *(float4*)(dst + 8)  = v2;
                *(float4*)(dst + 12) = v3;
                *(float4*)(dst + 16) = v4;
            }
        }
        __syncthreads();
    }

    if (!mode && blockIdx.x == 0) {
        if (tid < 512) gHfinal[tid] = sH[tid];
        if (tid < HID) dOut[1 + tid] = sH[tid];
    }
}

// =====================================================================
// K3: standalone logits kernel (fallback path only).
// =====================================================================
__global__ __launch_bounds__(512, 1) void logits_kernel(
    const float* __restrict__ outW, const float* __restrict__ outB,
    const int* __restrict__ target)
{
    const int t0 = blockIdx.y * 128;
    const int v0 = blockIdx.x * 128;

    __shared__ __align__(16) unsigned long long As[2][10][128];
    __shared__ __align__(16) unsigned long long Bs[2][10][128];
    __shared__ float sOb[128];
    __shared__ float sRowMax[128];
    __shared__ int   sRowIdx[128];

    const int tid = threadIdx.x;
    if (tid < 128) {
        int v = v0 + tid;
        sOb[tid] = (v < VOC) ? outB[v] : 0.f;
    }

    unsigned long long acc[4][8];
#pragma unroll
    for (int i = 0; i < 4; i++)
#pragma unroll
        for (int m = 0; m < 8; m++) acc[i][m] = 0ull;

    const int ty = tid >> 4, tx = tid & 15;

    {
#pragma unroll
        for (int r = 0; r < 5; r++) {
            int id = tid + r * 512;
            if (id < 1280) {
                int k2 = id >> 7, col = id & 127;
                float2 av = *(const float2*)(gDecHs + (size_t)(t0 + col) * HID + k2 * 2);
                As[0][k2][col] = f22ull(av.x, av.y);
            } else {
                int e = id - 1280;
                int k2 = e >> 7, col = e & 127;
                int v = v0 + col;
                float2 bv = make_float2(0.f, 0.f);
                if (v < VOC) bv = *(const float2*)(outW + (size_t)v * HID + k2 * 2);
                Bs[0][k2][col] = f22ull(bv.x, bv.y);
            }
        }
    }
    __syncthreads();

    for (int kc = 0; kc < 25; kc++) {
        const int cur = kc & 1, nxt = cur ^ 1;

        unsigned long long st[5];
        if (kc < 24) {
            const int kb = (kc + 1) * 20;
#pragma unroll
            for (int r = 0; r < 5; r++) {
                int id = tid + r * 512;
                if (id < 1280) {
                    int k2 = id >> 7, col = id & 127;
                    float2 av = *(const float2*)(gDecHs + (size_t)(t0 + col) * HID + kb + k2 * 2);
                    st[r] = f22ull(av.x, av.y);
                } else {
                    int e = id - 1280;
                    int k2 = e >> 7, col = e & 127;
                    int v = v0 + col;
                    float2 bv = make_float2(0.f, 0.f);
                    if (v < VOC) bv = *(const float2*)(outW + (size_t)v * HID + kb + k2 * 2);
                    st[r] = f22ull(bv.x, bv.y);
                }
            }
        }

#pragma unroll
        for (int k2 = 0; k2 < 10; k2++) {
            unsigned long long a[4], b[8];
            ulonglong2 q;
            const ulonglong2* ap = (const ulonglong2*)&As[cur][k2][ty << 2];
            q = ap[0]; a[0] = q.x; a[1] = q.y;
            q = ap[1]; a[2] = q.x; a[3] = q.y;
#pragma unroll
            for (int p = 0; p < 4; p++) {
                q = *(const ulonglong2*)&Bs[cur][k2][(tx << 1) + (p << 5)];
                b[p*2] = q.x; b[p*2+1] = q.y;
            }
#pragma unroll
            for (int i = 0; i < 4; i++)
#pragma unroll
                for (int m = 0; m < 8; m++) ffma2(acc[i][m], a[i], b[m]);
        }

        if (kc < 24) {
#pragma unroll
            for (int r = 0; r < 5; r++) {
                int id = tid + r * 512;
                if (id < 1280) {
                    int k2 = id >> 7, col = id & 127;
                    As[nxt][k2][col] = st[r];
                } else {
                    int e = id - 1280;
                    int k2 = e >> 7, col = e & 127;
                    Bs[nxt][k2][col] = st[r];
                }
            }
        }
        __syncthreads();
    }

    float* sM = (float*)As;
    int*   sI = (int*)Bs;

#pragma unroll
    for (int i = 0; i < 4; i++) {
        int row = (ty << 2) + i;
        int t = t0 + row;
        int tgt = target[t];
        float lmax = -1e30f; int lidx = 0;
#pragma unroll
        for (int m = 0; m < 8; m++) {
            int col = (tx << 1) + ((m >> 1) << 5) + (m & 1);
            int v = v0 + col;
            if (v < VOC) {
                float x, y; ull2f2(acc[i][m], x, y);
                float logit = x + y + sOb[col];
                if (logit > lmax) { lmax = logit; lidx = v; }
                if (v == tgt) gTlogit[t] = logit;
            }
        }
        sM[row * 16 + tx] = lmax;
        sI[row * 16 + tx] = lidx;
    }
    __syncthreads();

    if (tid < 128) {
        float m = -1e30f; int idx = 0x7fffffff;
        for (int e = 0; e < 16; e++) {
            float me = sM[tid * 16 + e]; int ie = sI[tid * 16 + e];
            if (me > m || (me == m && ie < idx)) { m = me; idx = ie; }
        }
        sRowMax[tid] = m; sRowIdx[tid] = idx;
    }
    __syncthreads();

    float* sS = (float*)Bs;
#pragma unroll
    for (int i = 0; i < 4; i++) {
        int row = (ty << 2) + i;
        float rmax = sRowMax[row];
        float lsum = 0.f;
#pragma unroll
        for (int m = 0; m < 8; m++) {
            int col = (tx << 1) + ((m >> 1) << 5) + (m & 1);
            int v = v0 + col;
            if (v < VOC) {
                float x, y; ull2f2(acc[i][m], x, y);
                lsum += __expf(x + y + sOb[col] - rmax);
            }
        }
        sS[row * 16 + tx] = lsum;
    }
    __syncthreads();

    if (tid < 128) {
        float s = 0.f;
        for (int e = 0; e < 16; e++) s += sS[tid * 16 + e];
        int t = t0 + tid;
        size_t o = (size_t)t * NVT + blockIdx.x;
        gPmax[o] = sRowMax[tid];
        gPidx[o] = sRowIdx[tid];
        gPsum[o] = s;
    }
}

// =====================================================================
// K4: per-row cross-tile reduction -> argmax + NLL.
// =====================================================================
__global__ __launch_bounds__(128) void finalize_kernel(float* __restrict__ dOut)
{
    const int t = blockIdx.x;
    const int tid = threadIdx.x;
    __shared__ float rm[128];
    __shared__ int   ri[128];
    __shared__ float rs[128];

    float m = -1e30f; int idx = 0x7fffffff;
    for (int vt = tid; vt < NVT; vt += 128) {
        float mv = gPmax[(size_t)t * NVT + vt];
        int   iv = gPidx[(size_t)t * NVT + vt];
        if (mv > m || (mv == m && iv < idx)) { m = mv; idx = iv; }
    }
    rm[tid] = m; ri[tid] = idx;
    __syncthreads();
    for (int off = 64; off; off >>= 1) {
        if (tid < off) {
            float m2 = rm[tid + off]; int i2 = ri[tid + off];
            if (m2 > rm[tid] || (m2 == rm[tid] && i2 < ri[tid])) { rm[tid] = m2; ri[tid] = i2; }
        }
        __syncthreads();
    }
    float gmax = rm[0]; int gidx = ri[0];

    float s = 0.f;
    for (int vt = tid; vt < NVT; vt += 128) {
        size_t o = (size_t)t * NVT + vt;
        s += gPsum[o] * expf(gPmax[o] - gmax);
    }
    rs[tid] = s;
    __syncthreads();
    for (int off = 64; off; off >>= 1) {
        if (tid < off) rs[tid] += rs[tid + off];
        __syncthreads();
    }
    if (tid == 0) {
        float lse = gmax + logf(rs[0]);
        gNll[t] = lse - gTlogit[t];
        dOut[1 + HID + t] = (float)gidx;
    }
}

// =====================================================================
// K5: loss = sum(gNll).
// =====================================================================
__global__ __launch_bounds__(512) void loss_kernel(float* __restrict__ dOut)
{
    __shared__ float rs[512];
    int tid = threadIdx.x;
    rs[tid] = gNll[tid];
    __syncthreads();
    for (int off = 256; off; off >>= 1) {
        if (tid < off) rs[tid] += rs[tid + off];
        __syncthreads();
    }
    if (tid == 0) dOut[0] = rs[0];
}

// =====================================================================
extern "C" void kernel_launch(void* const* d_in, const int* in_sizes, int n_in,
                              void* d_out, int out_size)
{
    const int*   encTok = (const int*)d_in[0];
    const int*   tgtTok = (const int*)d_in[1];
    const float* encH0  = (const float*)d_in[2];
    const float* encEmb = (const float*)d_in[3];
    const float* encWih = (const float*)d_in[4];
    const float* encWhh = (const float*)d_in[5];
    const float* encBih = (const float*)d_in[6];
    const float* encBhh = (const float*)d_in[7];
    const float* decEmb = (const float*)d_in[8];
    const float* decWih = (const float*)d_in[9];
    const float* decWhh = (const float*)d_in[10];
    const float* decBih = (const float*)d_in[11];
    const float* decBhh = (const float*)d_in[12];
    const float* outW   = (const float*)d_in[13];
    const float* outB   = (const float*)d_in[14];
    float* out = (float*)d_out;

    reset_kernel<<<2, 800>>>();
    gi_gemm_kernel<<<dim3(12, 4, 2), 256>>>(encTok, tgtTok, encEmb, decEmb,
                                            encWih, decWih, encBih, decBih);

    cudaFuncSetAttribute(gru_rec_cluster,
                         cudaFuncAttributeNonPortableClusterSizeAllowed, 1);
    cudaFuncSetAttribute(mega_kernel,
                         cudaFuncAttributeNonPortableClusterSizeAllowed, 1);

    cudaLaunchConfig_t cfg = {};
    cfg.gridDim  = dim3(CLN, 1, 1);
    cfg.blockDim = dim3(512, 1, 1);
    cfg.dynamicSmemBytes = 0;
    cfg.stream = 0;
    int maxC = 0;
    cudaOccupancyMaxPotentialClusterSize(&maxC, gru_rec_cluster, &cfg);

    cudaLaunchConfig_t cfg2 = {};
    cfg2.gridDim  = dim3(MGRID, 1, 1);
    cfg2.blockDim = dim3(512, 1, 1);
    cfg2.dynamicSmemBytes = 0;
    cfg2.stream = 0;
    int maxC2 = 0;
    cudaOccupancyMaxPotentialClusterSize(&maxC2, mega_kernel, &cfg2);

    if (maxC >= CLN && maxC2 >= CLN) {
        cudaLaunchAttribute at[1];
        at[0].id = cudaLaunchAttributeClusterDimension;
        at[0].val.clusterDim.x = CLN;
        at[0].val.clusterDim.y = 1;
        at[0].val.clusterDim.z = 1;
        cfg.attrs = at;  cfg.numAttrs = 1;
        cfg2.attrs = at; cfg2.numAttrs = 1;
        int m0 = 0;
        cudaLaunchKernelEx(&cfg, gru_rec_cluster, encWhh, encBhh, encH0, out, m0);
        cudaLaunchKernelEx(&cfg2, mega_kernel, decWhh, decBhh, outW, outB, tgtTok);
    } else {
        gru_rec_kernel<<<RBLK, 640>>>(encWhh, encBhh, encH0, out, 0, 0u);
        gru_rec_kernel<<<RBLK, 640>>>(decWhh, decBhh, encH0, out, 1, 512u);
        logits_kernel<<<dim3(NVT, 4), 512>>>(outW, outB, tgtTok);
    }

    finalize_kernel<<<512, 128>>>(out);
    loss_kernel<<<1, 512>>>(out);
}